// round 8
// baseline (speedup 1.0000x reference)
#include <cuda_runtime.h>
#include <cuda_fp16.h>
#include <math.h>

namespace {

constexpr int B_   = 4;
constexpr int TQ_  = 2048;
constexpr int TK_  = 2048;
constexpr int D_   = 1024;
constexpr int R_   = 64;
constexpr int H_   = 512;
constexpr int NF_  = D_ / 2 + 1;   // 513 rfft bins
constexpr int W2_  = 2 * NF_;      // 1026 (re | im)
constexpr int W2P_ = 1056;         // padded to multiple of 32 (BK)
constexpr int M_   = B_ * TQ_;     // 8192 rows

// ---------------- scratch ----------------------------------------------------
__device__ __align__(128) float g_CRI[D_ * W2P_];
__device__ __align__(128) float g_IMAT[W2P_ * D_];
__device__ __align__(128) float g_RoleN[R_ * D_];
__device__ __align__(128) float g_RNspec[R_ * W2P_];
__device__ __align__(128) float g_Q[M_ * D_];
__device__ __align__(128) float g_K[M_ * D_];
__device__ __align__(128) float g_V[M_ * D_];
__device__ __align__(128) float g_KB[M_ * D_];
__device__ __align__(128) float g_H1[M_ * H_];
__device__ __align__(128) float g_Wt[M_ * R_];
__device__ __align__(128) float g_Fr[(size_t)M_ * W2P_];
__device__ __align__(128) float g_Ka[(size_t)M_ * W2P_];
__device__ __align__(128) float g_P[(size_t)M_ * W2P_];   // pad cols never written -> stay 0
__device__ __align__(128) float g_S[(size_t)B_ * TQ_ * TK_];
__device__ __align__(128) float g_CTX[M_ * D_];
__device__ __align__(128) float g_qnorm[M_];
__device__ __align__(128) float g_rs[M_];
__device__ __align__(128) float g_tau[B_];

// ---------------- DFT matrix fill --------------------------------------------
__global__ void fill_fwd_dft() {
    int idx = blockIdx.x * blockDim.x + threadIdx.x;
    if (idx >= D_ * W2P_) return;
    int d = idx / W2P_, f = idx % W2P_;
    float v = 0.0f;
    if (f < W2_) {
        int fr = (f < NF_) ? f : (f - NF_);
        int m  = (int)(((long long)fr * d) % D_);
        float a = (float)m * (6.283185307179586f / (float)D_);
        v = (f < NF_) ? cosf(a) : -sinf(a);
    }
    g_CRI[idx] = v;
}

__global__ void fill_inv_dft() {
    int idx = blockIdx.x * blockDim.x + threadIdx.x;
    if (idx >= W2P_ * D_) return;
    int f = idx / D_, d = idx % D_;
    float v = 0.0f;
    if (f < W2_) {
        int fr = (f < NF_) ? f : (f - NF_);
        int m  = (int)(((long long)fr * d) % D_);
        float a = (float)m * (6.283185307179586f / (float)D_);
        if (f < NF_) {
            float c = (fr == 0 || fr == D_ / 2) ? 1.0f : 2.0f;
            v = c * cosf(a) * (1.0f / (float)D_);
        } else {
            v = (fr == 0 || fr == D_ / 2) ? 0.0f : (-2.0f / (float)D_) * sinf(a);
        }
    }
    g_IMAT[idx] = v;
}

// ---------------- row l2-normalize -------------------------------------------
__global__ void rownorm_kernel(const float* __restrict__ in, float* __restrict__ out,
                               float* __restrict__ norms, int cols) {
    int row = blockIdx.x;
    const float* p = in + (size_t)row * cols;
    float s = 0.0f;
    for (int c = threadIdx.x; c < cols; c += blockDim.x) { float v = p[c]; s += v * v; }
    __shared__ float red[256];
    red[threadIdx.x] = s;
    __syncthreads();
    for (int o = 128; o > 0; o >>= 1) {
        if (threadIdx.x < o) red[threadIdx.x] += red[threadIdx.x + o];
        __syncthreads();
    }
    float nrm = sqrtf(red[0]);
    if (threadIdx.x == 0 && norms) norms[row] = nrm;
    float inv = 1.0f / fmaxf(nrm, 1e-12f);
    float* q = out + (size_t)row * cols;
    for (int c = threadIdx.x; c < cols; c += blockDim.x) q[c] = p[c] * inv;
}

// ---------------- astrocyte state + tau --------------------------------------
__global__ void astro_kernel(const float* __restrict__ qnorm,
                             const float* __restrict__ astro_in,
                             const float* __restrict__ astro_scale,
                             float* __restrict__ out_state) {
    int b = blockIdx.x;
    float s = 0.0f;
    for (int t = threadIdx.x; t < TQ_; t += blockDim.x) s += qnorm[b * TQ_ + t];
    __shared__ float red[256];
    red[threadIdx.x] = s;
    __syncthreads();
    for (int o = 128; o > 0; o >>= 1) {
        if (threadIdx.x < o) red[threadIdx.x] += red[threadIdx.x + o];
        __syncthreads();
    }
    if (threadIdx.x == 0) {
        float mean_surprise = red[0] / (32.0f * (float)TQ_);
        float ns = 0.95f * astro_in[b] + 0.05f * mean_surprise;
        g_tau[b] = fmaxf(1.0f + astro_scale[0] * ns, 0.001f);
        out_state[b] = ns;
    }
}

// ---------------- softmax over R=64 ------------------------------------------
__global__ void softmax64(float* __restrict__ x) {
    int warp = (blockIdx.x * blockDim.x + threadIdx.x) >> 5;
    int lane = threadIdx.x & 31;
    if (warp >= M_) return;
    float* p = x + (size_t)warp * R_;
    float v0 = p[lane], v1 = p[lane + 32];
    float m = fmaxf(v0, v1);
    #pragma unroll
    for (int o = 16; o > 0; o >>= 1) m = fmaxf(m, __shfl_xor_sync(0xffffffffu, m, o));
    float e0 = expf(v0 - m), e1 = expf(v1 - m);
    float sum = e0 + e1;
    #pragma unroll
    for (int o = 16; o > 0; o >>= 1) sum += __shfl_xor_sync(0xffffffffu, sum, o);
    float inv = 1.0f / sum;
    p[lane] = e0 * inv;
    p[lane + 32] = e1 * inv;
}

// ---------------- complex elementwise product --------------------------------
__global__ void cmul_kernel() {
    long long i = (long long)blockIdx.x * blockDim.x + threadIdx.x;
    if (i >= (long long)M_ * NF_) return;
    long long row = i / NF_;
    int f = (int)(i % NF_);
    const float* a = g_Ka + row * W2P_;
    const float* b = g_Fr + row * W2P_;
    float ar = a[f], ai = a[NF_ + f];
    float br = b[f], bi = b[NF_ + f];
    g_P[row * W2P_ + f]       = ar * br - ai * bi;
    g_P[row * W2P_ + NF_ + f] = ar * bi + ai * br;
}

// ---------------- score row-sum ----------------------------------------------
__global__ void rowsum_kernel(const float* __restrict__ S, float* __restrict__ rs) {
    int row = blockIdx.x;
    const float* p = S + (size_t)row * TK_;
    float s = 0.0f;
    for (int c = threadIdx.x; c < TK_; c += blockDim.x) s += p[c];
    __shared__ float red[256];
    red[threadIdx.x] = s;
    __syncthreads();
    for (int o = 128; o > 0; o >>= 1) {
        if (threadIdx.x < o) red[threadIdx.x] += red[threadIdx.x + o];
        __syncthreads();
    }
    if (threadIdx.x == 0) rs[row] = fmaxf(red[0], 1e-9f);
}

// ---------------- fp16 helpers -----------------------------------------------
__device__ __forceinline__ void mma16(float* c, const unsigned* a, unsigned b0, unsigned b1) {
    asm volatile(
        "mma.sync.aligned.m16n8k16.row.col.f32.f16.f16.f32 "
        "{%0,%1,%2,%3},{%4,%5,%6,%7},{%8,%9},{%0,%1,%2,%3};"
        : "+f"(c[0]), "+f"(c[1]), "+f"(c[2]), "+f"(c[3])
        : "r"(a[0]), "r"(a[1]), "r"(a[2]), "r"(a[3]), "r"(b0), "r"(b1));
}

// ---------------- fp16 tensor-core GEMM (legacy HMMA.16816) ------------------
// C[M,N] = A[M,K] (row-major) * B (K-major if !TRB, [N][K] if TRB)
// EPI: 0=none, 1=+bias, 2=relu(+bias), 3=Epanechnikov (bias=tau[z]), 4=/aux[z*M+row]
// PASSES: 1 = single fp16, 3 = fp16x3 split (fp32-class accuracy)
template <int EPI, bool TRB, int PASSES>
__global__ void __launch_bounds__(256) mma_gemm(
    const float* __restrict__ Ag, const float* __restrict__ Bg, float* __restrict__ Cg,
    int M, int N, int K, long long sA, long long sB, long long sC,
    const float* __restrict__ bias, const float* __restrict__ aux) {
    constexpr int BM = 128, BN = 128, BK = 32;
    constexpr int AP = BK + 8;      // 40-half stride (80B) -> conflict-free frags
    constexpr int NBUF = (PASSES == 3) ? 2 : 1;
    __shared__ __half As[NBUF][BM * AP];
    __shared__ __half Bs[NBUF][BN * AP];

    const int z = blockIdx.z;
    const float* A = Ag + (long long)z * sA;
    const float* B = Bg + (long long)z * sB;
    float* C = Cg + (long long)z * sC;

    const int rowBase = blockIdx.y * BM;
    const int colBase = blockIdx.x * BN;
    const int tid = threadIdx.x;
    const int lane = tid & 31, warp = tid >> 5;
    const int wm = warp >> 1, wn = warp & 1;  // 4 x 2 warp grid
    const int lrow = lane >> 2, lcol = lane & 3;
    const bool fullTile = (rowBase + BM <= M) && (colBase + BN <= N);

    float acc[2][8][4];
    #pragma unroll
    for (int i = 0; i < 2; i++)
        #pragma unroll
        for (int j = 0; j < 8; j++)
            #pragma unroll
            for (int e = 0; e < 4; e++) acc[i][j][e] = 0.0f;

    // staging indices: each thread handles 16 floats per tensor
    const int ar = tid >> 1, as_ = (tid & 1) * 16;        // A (and B if TRB)
    const int bkl = tid >> 3, bnl = (tid & 7) * 16;       // B if !TRB

    float4 stA[4], stB[4];
    const float4 zero4 = make_float4(0.f, 0.f, 0.f, 0.f);

    auto ldA = [&](int kt) {
        int gm = rowBase + ar;
        const float* src = A + (long long)gm * K + kt + as_;
        #pragma unroll
        for (int j = 0; j < 4; j++)
            stA[j] = (gm < M) ? *reinterpret_cast<const float4*>(src + j * 4) : zero4;
    };
    auto ldB = [&](int kt) {
        if (!TRB) {
            int gn = colBase + bnl;
            const float* src = B + (long long)(kt + bkl) * N + gn;
            #pragma unroll
            for (int j = 0; j < 4; j++)
                stB[j] = (gn < N) ? *reinterpret_cast<const float4*>(src + j * 4) : zero4;
        } else {
            int gn = colBase + ar;
            const float* src = B + (long long)gn * K + kt + as_;
            #pragma unroll
            for (int j = 0; j < 4; j++)
                stB[j] = (gn < N) ? *reinterpret_cast<const float4*>(src + j * 4) : zero4;
        }
    };
    auto stage = [&]() {
        {   // A: contiguous 16 halves at [ar][as_..as_+15]
            const float* f = reinterpret_cast<const float*>(stA);
            union { __half h[16]; uint4 u[2]; } Hh, Ll;
            #pragma unroll
            for (int j = 0; j < 16; j++) {
                __half h = __float2half_rn(f[j]);
                Hh.h[j] = h;
                if (PASSES == 3) Ll.h[j] = __float2half_rn(f[j] - __half2float(h));
            }
            int base = ar * AP + as_;
            *reinterpret_cast<uint4*>(&As[0][base]) = Hh.u[0];
            *reinterpret_cast<uint4*>(&As[0][base + 8]) = Hh.u[1];
            if (PASSES == 3) {
                *reinterpret_cast<uint4*>(&As[1][base]) = Ll.u[0];
                *reinterpret_cast<uint4*>(&As[1][base + 8]) = Ll.u[1];
            }
        }
        if (!TRB) {  // scatter 16 cols into Bs[n][k]
            if (colBase + bnl < N) {
                const float* f = reinterpret_cast<const float*>(stB);
                #pragma unroll
                for (int j = 0; j < 16; j++) {
                    __half h = __float2half_rn(f[j]);
                    Bs[0][(bnl + j) * AP + bkl] = h;
                    if (PASSES == 3)
                        Bs[1][(bnl + j) * AP + bkl] = __float2half_rn(f[j] - __half2float(h));
                }
            }
        } else {     // contiguous 16 halves at [ar][as_..]
            const float* f = reinterpret_cast<const float*>(stB);
            union { __half h[16]; uint4 u[2]; } Hh, Ll;
            #pragma unroll
            for (int j = 0; j < 16; j++) {
                __half h = __float2half_rn(f[j]);
                Hh.h[j] = h;
                if (PASSES == 3) Ll.h[j] = __float2half_rn(f[j] - __half2float(h));
            }
            int base = ar * AP + as_;
            *reinterpret_cast<uint4*>(&Bs[0][base]) = Hh.u[0];
            *reinterpret_cast<uint4*>(&Bs[0][base + 8]) = Hh.u[1];
            if (PASSES == 3) {
                *reinterpret_cast<uint4*>(&Bs[1][base]) = Ll.u[0];
                *reinterpret_cast<uint4*>(&Bs[1][base + 8]) = Ll.u[1];
            }
        }
    };

    ldA(0); ldB(0);
    for (int kt = 0; kt < K; kt += BK) {
        __syncthreads();
        stage();
        __syncthreads();
        if (kt + BK < K) { ldA(kt + BK); ldB(kt + BK); }
        #pragma unroll
        for (int ks = 0; ks < 2; ks++) {
            const int koff = ks * 16 + lcol * 2;
            unsigned ah[2][4], al[2][4];
            #pragma unroll
            for (int mt = 0; mt < 2; mt++) {
                int mb = (wm * 32 + mt * 16 + lrow) * AP + koff;
                ah[mt][0] = *reinterpret_cast<const unsigned*>(&As[0][mb]);
                ah[mt][1] = *reinterpret_cast<const unsigned*>(&As[0][mb + 8 * AP]);
                ah[mt][2] = *reinterpret_cast<const unsigned*>(&As[0][mb + 8]);
                ah[mt][3] = *reinterpret_cast<const unsigned*>(&As[0][mb + 8 * AP + 8]);
                if (PASSES == 3) {
                    al[mt][0] = *reinterpret_cast<const unsigned*>(&As[1][mb]);
                    al[mt][1] = *reinterpret_cast<const unsigned*>(&As[1][mb + 8 * AP]);
                    al[mt][2] = *reinterpret_cast<const unsigned*>(&As[1][mb + 8]);
                    al[mt][3] = *reinterpret_cast<const unsigned*>(&As[1][mb + 8 * AP + 8]);
                }
            }
            #pragma unroll
            for (int nt = 0; nt < 8; nt++) {
                int nb = (wn * 64 + nt * 8 + lrow) * AP + koff;
                unsigned bh0 = *reinterpret_cast<const unsigned*>(&Bs[0][nb]);
                unsigned bh1 = *reinterpret_cast<const unsigned*>(&Bs[0][nb + 8]);
                #pragma unroll
                for (int mt = 0; mt < 2; mt++) mma16(acc[mt][nt], ah[mt], bh0, bh1);
                if (PASSES == 3) {
                    unsigned bl0 = *reinterpret_cast<const unsigned*>(&Bs[1][nb]);
                    unsigned bl1 = *reinterpret_cast<const unsigned*>(&Bs[1][nb + 8]);
                    #pragma unroll
                    for (int mt = 0; mt < 2; mt++) {
                        mma16(acc[mt][nt], al[mt], bh0, bh1);
                        mma16(acc[mt][nt], ah[mt], bl0, bl1);
                    }
                }
            }
        }
    }

    float tau = (EPI == 3) ? bias[z] : 0.0f;
    #pragma unroll
    for (int mt = 0; mt < 2; mt++) {
        int gm0 = rowBase + wm * 32 + mt * 16 + lrow;
        int gm1 = gm0 + 8;
        float rd0 = 1.0f, rd1 = 1.0f;
        if (EPI == 4) {
            if (fullTile || gm0 < M) rd0 = 1.0f / aux[(long long)z * M + gm0];
            if (fullTile || gm1 < M) rd1 = 1.0f / aux[(long long)z * M + gm1];
        }
        #pragma unroll
        for (int nt = 0; nt < 8; nt++) {
            int gc = colBase + wn * 64 + nt * 8 + lcol * 2;
            #pragma unroll
            for (int e = 0; e < 4; e++) {
                int gm = (e < 2) ? gm0 : gm1;
                int gn = gc + (e & 1);
                if (!fullTile && (gm >= M || gn >= N)) continue;
                float v = acc[mt][nt][e];
                if (EPI == 1) v += bias[gn];
                else if (EPI == 2) v = fmaxf(v + bias[gn], 0.0f);
                else if (EPI == 3) {
                    float x = (v + 1.0f) * 0.5f;
                    float d = 1.0f - x;
                    v = fmaxf(1.0f - tau * d * d, 0.0f);
                } else if (EPI == 4) v *= (e < 2) ? rd0 : rd1;
                C[(long long)gm * N + gn] = v;
            }
        }
    }
}

static float* sym(const void* s) {
    void* p = nullptr;
    cudaGetSymbolAddress(&p, s);
    return (float*)p;
}

}  // namespace

extern "C" void kernel_launch(void* const* d_in, const int* in_sizes, int n_in,
                              void* d_out, int out_size) {
    const float* q_in  = (const float*)d_in[0];
    const float* k_in  = (const float*)d_in[1];
    const float* v_in  = (const float*)d_in[2];
    const float* astro = (const float*)d_in[3];
    const float* Wq = (const float*)d_in[4];
    const float* bq = (const float*)d_in[5];
    const float* Wk = (const float*)d_in[6];
    const float* bk = (const float*)d_in[7];
    const float* Wv = (const float*)d_in[8];
    const float* bv = (const float*)d_in[9];
    const float* Wo = (const float*)d_in[10];
    const float* bo = (const float*)d_in[11];
    const float* role_matrix = (const float*)d_in[12];
    const float* Wr1 = (const float*)d_in[13];
    const float* br1 = (const float*)d_in[14];
    const float* Wr2 = (const float*)d_in[15];
    const float* astro_scale = (const float*)d_in[16];
    float* out = (float*)d_out;

    float* CRI    = sym(g_CRI);
    float* IMAT   = sym(g_IMAT);
    float* RoleN  = sym(g_RoleN);
    float* RNspec = sym(g_RNspec);
    float* Q      = sym(g_Q);
    float* Kp     = sym(g_K);
    float* Vp     = sym(g_V);
    float* KB     = sym(g_KB);
    float* H1     = sym(g_H1);
    float* Wt     = sym(g_Wt);
    float* Fr     = sym(g_Fr);
    float* Ka     = sym(g_Ka);
    float* P      = sym(g_P);
    float* S      = sym(g_S);
    float* CTX    = sym(g_CTX);
    float* qnorm  = sym(g_qnorm);
    float* rs     = sym(g_rs);
    float* tau    = sym(g_tau);

    // 1. DFT matrices
    fill_fwd_dft<<<(D_ * W2P_ + 255) / 256, 256>>>();
    fill_inv_dft<<<(W2P_ * D_ + 255) / 256, 256>>>();

    // 2. role rows normalize + spectra
    rownorm_kernel<<<R_, 256>>>(role_matrix, RoleN, nullptr, D_);
    mma_gemm<0, false, 1><<<dim3(9, 1, 1), 256>>>(
        RoleN, CRI, RNspec, R_, W2P_, D_, 0, 0, 0, nullptr, nullptr);

    // 3. Q, K, V projections (V is on the value path -> fp16x3)
    mma_gemm<1, false, 1><<<dim3(8, 64, 1), 256>>>(q_in, Wq, Q,  M_, D_, D_, 0, 0, 0, bq, nullptr);
    mma_gemm<1, false, 1><<<dim3(8, 64, 1), 256>>>(k_in, Wk, Kp, M_, D_, D_, 0, 0, 0, bk, nullptr);
    mma_gemm<1, false, 3><<<dim3(8, 64, 1), 256>>>(v_in, Wv, Vp, M_, D_, D_, 0, 0, 0, bv, nullptr);

    // 4. surprise + astro state
    rownorm_kernel<<<M_, 256>>>(Q, Q, qnorm, D_);
    astro_kernel<<<B_, 256>>>(qnorm, astro, astro_scale, out + (out_size - B_));

    // 5. role MLP -> softmax weights
    mma_gemm<2, false, 1><<<dim3(4, 64, 1), 256>>>(Kp, Wr1, H1, M_, H_, D_, 0, 0, 0, br1, nullptr);
    mma_gemm<0, false, 1><<<dim3(1, 64, 1), 256>>>(H1, Wr2, Wt, M_, R_, H_, 0, 0, 0, nullptr, nullptr);
    softmax64<<<M_ / 8, 256>>>(Wt);

    // 6. holographic binding in frequency domain
    mma_gemm<0, false, 1><<<dim3(9, 64, 1), 256>>>(
        Wt, RNspec, Fr, M_, W2P_, R_, 0, 0, 0, nullptr, nullptr);
    mma_gemm<0, false, 1><<<dim3(9, 64, 1), 256>>>(
        Kp, CRI, Ka, M_, W2P_, D_, 0, 0, 0, nullptr, nullptr);
    cmul_kernel<<<(int)(((long long)M_ * NF_ + 255) / 256), 256>>>();
    mma_gemm<0, false, 1><<<dim3(8, 64, 1), 256>>>(
        P, IMAT, KB, M_, D_, W2P_, 0, 0, 0, nullptr, nullptr);

    // 7. normalize K_bound
    rownorm_kernel<<<M_, 256>>>(KB, KB, nullptr, D_);

    // 8. Epanechnikov scores on cosine sim (fp16x3 for accuracy margin)
    mma_gemm<3, true, 3><<<dim3(16, 16, B_), 256>>>(
        Q, KB, S, TQ_, TK_, D_,
        (long long)TQ_ * D_, (long long)TK_ * D_, (long long)TQ_ * TK_, tau, nullptr);

    // 9. denominators, then context = (S @ V) / rowsum   (value path -> fp16x3)
    rowsum_kernel<<<M_, 256>>>(S, rs);
    mma_gemm<4, false, 3><<<dim3(8, 16, B_), 256>>>(
        S, Vp, CTX, TQ_, D_, TK_,
        (long long)TQ_ * TK_, (long long)TK_ * D_, (long long)TQ_ * D_, nullptr, rs);

    // 10. output projection (value path -> fp16x3)
    mma_gemm<1, false, 3><<<dim3(8, 64, 1), 256>>>(CTX, Wo, out, M_, D_, D_, 0, 0, 0, bo, nullptr);
}

// round 9
// speedup vs baseline: 2.0007x; 2.0007x over previous
#include <cuda_runtime.h>
#include <math.h>

namespace {

constexpr int B_   = 4;
constexpr int TQ_  = 2048;
constexpr int TK_  = 2048;
constexpr int D_   = 1024;
constexpr int R_   = 64;
constexpr int H_   = 512;
constexpr int NF_  = D_ / 2 + 1;   // 513 rfft bins
constexpr int W2_  = 2 * NF_;      // 1026 (re | im)
constexpr int W2P_ = 1056;         // padded to multiple of BK=32
constexpr int M_   = B_ * TQ_;     // 8192 rows

// ---------------- scratch ----------------------------------------------------
__device__ __align__(128) float g_CRI[D_ * W2P_];
__device__ __align__(128) float g_IMAT[W2P_ * D_];
__device__ __align__(128) float g_RoleN[R_ * D_];
__device__ __align__(128) float g_RNspec[R_ * W2P_];
__device__ __align__(128) float g_Q[M_ * D_];
__device__ __align__(128) float g_K[M_ * D_];
__device__ __align__(128) float g_V[M_ * D_];
__device__ __align__(128) float g_KB[M_ * D_];
__device__ __align__(128) float g_H1[M_ * H_];
__device__ __align__(128) float g_Wt[M_ * R_];
__device__ __align__(128) float g_Fr[(size_t)M_ * W2P_];
__device__ __align__(128) float g_Ka[(size_t)M_ * W2P_];
__device__ __align__(128) float g_P[(size_t)M_ * W2P_];   // pad cols never written -> stay 0
__device__ __align__(128) float g_S[(size_t)B_ * TQ_ * TK_];
__device__ __align__(128) float g_CTX[M_ * D_];
__device__ __align__(128) float g_qnorm[M_];
__device__ __align__(128) float g_rs[M_];
__device__ __align__(128) float g_tau[B_];

// ---------------- DFT matrix fill --------------------------------------------
__global__ void fill_fwd_dft() {
    int idx = blockIdx.x * blockDim.x + threadIdx.x;
    if (idx >= D_ * W2P_) return;
    int d = idx / W2P_, f = idx % W2P_;
    float v = 0.0f;
    if (f < W2_) {
        int fr = (f < NF_) ? f : (f - NF_);
        int m  = (int)(((long long)fr * d) % D_);
        float a = (float)m * (6.283185307179586f / (float)D_);
        v = (f < NF_) ? cosf(a) : -sinf(a);
    }
    g_CRI[idx] = v;
}

__global__ void fill_inv_dft() {
    int idx = blockIdx.x * blockDim.x + threadIdx.x;
    if (idx >= W2P_ * D_) return;
    int f = idx / D_, d = idx % D_;
    float v = 0.0f;
    if (f < W2_) {
        int fr = (f < NF_) ? f : (f - NF_);
        int m  = (int)(((long long)fr * d) % D_);
        float a = (float)m * (6.283185307179586f / (float)D_);
        if (f < NF_) {
            float c = (fr == 0 || fr == D_ / 2) ? 1.0f : 2.0f;
            v = c * cosf(a) * (1.0f / (float)D_);
        } else {
            v = (fr == 0 || fr == D_ / 2) ? 0.0f : (-2.0f / (float)D_) * sinf(a);
        }
    }
    g_IMAT[idx] = v;
}

// ---------------- row l2-normalize -------------------------------------------
__global__ void rownorm_kernel(const float* __restrict__ in, float* __restrict__ out,
                               float* __restrict__ norms, int cols) {
    int row = blockIdx.x;
    const float* p = in + (size_t)row * cols;
    float s = 0.0f;
    for (int c = threadIdx.x; c < cols; c += blockDim.x) { float v = p[c]; s += v * v; }
    __shared__ float red[256];
    red[threadIdx.x] = s;
    __syncthreads();
    for (int o = 128; o > 0; o >>= 1) {
        if (threadIdx.x < o) red[threadIdx.x] += red[threadIdx.x + o];
        __syncthreads();
    }
    float nrm = sqrtf(red[0]);
    if (threadIdx.x == 0 && norms) norms[row] = nrm;
    float inv = 1.0f / fmaxf(nrm, 1e-12f);
    float* q = out + (size_t)row * cols;
    for (int c = threadIdx.x; c < cols; c += blockDim.x) q[c] = p[c] * inv;
}

// ---------------- astrocyte state + tau --------------------------------------
__global__ void astro_kernel(const float* __restrict__ qnorm,
                             const float* __restrict__ astro_in,
                             const float* __restrict__ astro_scale,
                             float* __restrict__ out_state) {
    int b = blockIdx.x;
    float s = 0.0f;
    for (int t = threadIdx.x; t < TQ_; t += blockDim.x) s += qnorm[b * TQ_ + t];
    __shared__ float red[256];
    red[threadIdx.x] = s;
    __syncthreads();
    for (int o = 128; o > 0; o >>= 1) {
        if (threadIdx.x < o) red[threadIdx.x] += red[threadIdx.x + o];
        __syncthreads();
    }
    if (threadIdx.x == 0) {
        float mean_surprise = red[0] / (32.0f * (float)TQ_);
        float ns = 0.95f * astro_in[b] + 0.05f * mean_surprise;
        g_tau[b] = fmaxf(1.0f + astro_scale[0] * ns, 0.001f);
        out_state[b] = ns;
    }
}

// ---------------- softmax over R=64 ------------------------------------------
__global__ void softmax64(float* __restrict__ x) {
    int warp = (blockIdx.x * blockDim.x + threadIdx.x) >> 5;
    int lane = threadIdx.x & 31;
    if (warp >= M_) return;
    float* p = x + (size_t)warp * R_;
    float v0 = p[lane], v1 = p[lane + 32];
    float m = fmaxf(v0, v1);
    #pragma unroll
    for (int o = 16; o > 0; o >>= 1) m = fmaxf(m, __shfl_xor_sync(0xffffffffu, m, o));
    float e0 = expf(v0 - m), e1 = expf(v1 - m);
    float sum = e0 + e1;
    #pragma unroll
    for (int o = 16; o > 0; o >>= 1) sum += __shfl_xor_sync(0xffffffffu, sum, o);
    float inv = 1.0f / sum;
    p[lane] = e0 * inv;
    p[lane + 32] = e1 * inv;
}

// ---------------- complex elementwise product --------------------------------
__global__ void cmul_kernel() {
    long long i = (long long)blockIdx.x * blockDim.x + threadIdx.x;
    if (i >= (long long)M_ * NF_) return;
    long long row = i / NF_;
    int f = (int)(i % NF_);
    const float* a = g_Ka + row * W2P_;
    const float* b = g_Fr + row * W2P_;
    float ar = a[f], ai = a[NF_ + f];
    float br = b[f], bi = b[NF_ + f];
    g_P[row * W2P_ + f]       = ar * br - ai * bi;
    g_P[row * W2P_ + NF_ + f] = ar * bi + ai * br;
}

// ---------------- score row-sum ----------------------------------------------
__global__ void rowsum_kernel(const float* __restrict__ S, float* __restrict__ rs) {
    int row = blockIdx.x;
    const float* p = S + (size_t)row * TK_;
    float s = 0.0f;
    for (int c = threadIdx.x; c < TK_; c += blockDim.x) s += p[c];
    __shared__ float red[256];
    red[threadIdx.x] = s;
    __syncthreads();
    for (int o = 128; o > 0; o >>= 1) {
        if (threadIdx.x < o) red[threadIdx.x] += red[threadIdx.x + o];
        __syncthreads();
    }
    if (threadIdx.x == 0) rs[row] = fmaxf(red[0], 1e-9f);
}

// ---------------- tf32 / cp.async helpers ------------------------------------
__device__ __forceinline__ unsigned tf32u(float x) {
    unsigned u;
    asm("cvt.rna.tf32.f32 %0, %1;" : "=r"(u) : "f"(x));
    return u;
}
__device__ __forceinline__ void cpa16(float* dst, const float* src, int sz) {
    unsigned d = (unsigned)__cvta_generic_to_shared(dst);
    asm volatile("cp.async.cg.shared.global [%0], [%1], 16, %2;" :: "r"(d), "l"(src), "r"(sz));
}
__device__ __forceinline__ void cp_commit() { asm volatile("cp.async.commit_group;"); }
__device__ __forceinline__ void cp_wait0()  { asm volatile("cp.async.wait_group 0;"); }

__device__ __forceinline__ void mma8(float* c, const unsigned* a, unsigned b0, unsigned b1) {
    asm volatile(
        "mma.sync.aligned.m16n8k8.row.col.f32.tf32.tf32.f32 "
        "{%0,%1,%2,%3},{%4,%5,%6,%7},{%8,%9},{%0,%1,%2,%3};"
        : "+f"(c[0]), "+f"(c[1]), "+f"(c[2]), "+f"(c[3])
        : "r"(a[0]), "r"(a[1]), "r"(a[2]), "r"(a[3]), "r"(b0), "r"(b1));
}

// hi = mantissa-truncated value (exact split: v = hi + lo). Raw bits feed tf32 mma.
__device__ __forceinline__ unsigned hibits(float v) { return __float_as_uint(v) & 0xFFFFE000u; }

// ---------------- tf32 tensor-core GEMM v2 (cp.async double-buffered) --------
// C[M,N] = A[M,K] row-major times B (B[K][N] if !TRB, B[N][K] if TRB)
// EPI: 0=none, 1=+bias, 2=relu(+bias), 3=Epanechnikov (bias=tau[z]), 4=/aux[z*M+row]
// PASSES: 1 = single tf32 (cvt.rna), 3 = split x3 (exact hi/lo, fp32-class)
template <int EPI, bool TRB, int PASSES>
__global__ void __launch_bounds__(256, 2) mma_gemm(
    const float* __restrict__ Ag, const float* __restrict__ Bg, float* __restrict__ Cg,
    int M, int N, int K, long long sA, long long sB, long long sC,
    const float* __restrict__ bias, const float* __restrict__ aux) {
    constexpr int BM = 128, BN = 128, BK = 32;
    constexpr int AP  = 36;    // row stride (floats) for [row][k] tiles; 144B, 16B-aligned
    constexpr int BPK = 136;   // row stride for [k][n] tile; 544B, 16B-aligned
    constexpr int ASZ = BM * AP;                       // 4608 floats / buffer
    constexpr int BSZ = TRB ? (BN * AP) : (BK * BPK);  // 4608 or 4352
    extern __shared__ float sm[];
    float* As = sm;              // [2][ASZ]
    float* Bs = sm + 2 * ASZ;    // [2][BSZ]

    const int z = blockIdx.z;
    const float* A = Ag + (long long)z * sA;
    const float* B = Bg + (long long)z * sB;
    float* C = Cg + (long long)z * sC;

    const int rowBase = blockIdx.y * BM;
    const int colBase = blockIdx.x * BN;
    const int tid = threadIdx.x;
    const int lane = tid & 31, warp = tid >> 5;
    const int wm = warp >> 1, wn = warp & 1;  // 4 x 2 warp grid
    const int lrow = lane >> 2, lcol = lane & 3;
    const bool fullTile = (rowBase + BM <= M) && (colBase + BN <= N);

    float acc[2][8][4];
    #pragma unroll
    for (int i = 0; i < 2; i++)
        #pragma unroll
        for (int j = 0; j < 8; j++)
            #pragma unroll
            for (int e = 0; e < 4; e++) acc[i][j][e] = 0.0f;

    auto issue = [&](int ch) {
        const int kt = ch * BK;
        float* dA = As + (ch & 1) * ASZ;
        float* dB = Bs + (ch & 1) * BSZ;
        #pragma unroll
        for (int i = 0; i < 4; i++) {        // A: 128 rows x 32 k
            int id = i * 256 + tid;
            int row = id >> 3, c4 = (id & 7) * 4;
            int gm = rowBase + row;
            const float* src = A + (long long)(gm < M ? gm : 0) * K + kt + c4;
            cpa16(dA + row * AP + c4, src, (gm < M) ? 16 : 0);
        }
        if (!TRB) {
            #pragma unroll
            for (int i = 0; i < 4; i++) {    // B: 32 k x 128 n
                int id = i * 256 + tid;
                int k = id >> 5, n4 = (id & 31) * 4;
                int gn = colBase + n4;
                const float* src = B + (long long)(kt + k) * N + (gn < N ? gn : 0);
                cpa16(dB + k * BPK + n4, src, (gn < N) ? 16 : 0);
            }
        } else {
            #pragma unroll
            for (int i = 0; i < 4; i++) {    // B: 128 n-rows x 32 k
                int id = i * 256 + tid;
                int row = id >> 3, c4 = (id & 7) * 4;
                int gn = colBase + row;
                const float* src = B + (long long)(gn < N ? gn : 0) * K + kt + c4;
                cpa16(dB + row * AP + c4, src, (gn < N) ? 16 : 0);
            }
        }
        cp_commit();
    };

    const int nch = K / BK;
    issue(0);
    for (int ch = 0; ch < nch; ch++) {
        cp_wait0();
        __syncthreads();
        if (ch + 1 < nch) issue(ch + 1);
        const float* Ab = As + (ch & 1) * ASZ;
        const float* Bb = Bs + (ch & 1) * BSZ;
        #pragma unroll
        for (int ks = 0; ks < 4; ks++) {
            const int k0 = ks * 8;
            unsigned ah[2][4], al[2][4];
            #pragma unroll
            for (int mt = 0; mt < 2; mt++) {
                const float* ap = Ab + (wm * 32 + mt * 16 + lrow) * AP + k0 + lcol;
                float v0 = ap[0], v1 = ap[8 * AP], v2 = ap[4], v3 = ap[8 * AP + 4];
                if (PASSES == 3) {
                    ah[mt][0] = hibits(v0); ah[mt][1] = hibits(v1);
                    ah[mt][2] = hibits(v2); ah[mt][3] = hibits(v3);
                    al[mt][0] = __float_as_uint(v0 - __uint_as_float(ah[mt][0]));
                    al[mt][1] = __float_as_uint(v1 - __uint_as_float(ah[mt][1]));
                    al[mt][2] = __float_as_uint(v2 - __uint_as_float(ah[mt][2]));
                    al[mt][3] = __float_as_uint(v3 - __uint_as_float(ah[mt][3]));
                } else {
                    ah[mt][0] = tf32u(v0); ah[mt][1] = tf32u(v1);
                    ah[mt][2] = tf32u(v2); ah[mt][3] = tf32u(v3);
                }
            }
            #pragma unroll
            for (int nt = 0; nt < 8; nt++) {
                float w0, w1;
                if (!TRB) {
                    const float* bp = Bb + (k0 + lcol) * BPK + wn * 64 + nt * 8 + lrow;
                    w0 = bp[0]; w1 = bp[4 * BPK];
                } else {
                    const float* bp = Bb + (wn * 64 + nt * 8 + lrow) * AP + k0 + lcol;
                    w0 = bp[0]; w1 = bp[4];
                }
                if (PASSES == 3) {
                    unsigned bh0 = hibits(w0), bh1 = hibits(w1);
                    unsigned bl0 = __float_as_uint(w0 - __uint_as_float(bh0));
                    unsigned bl1 = __float_as_uint(w1 - __uint_as_float(bh1));
                    #pragma unroll
                    for (int mt = 0; mt < 2; mt++) {
                        mma8(acc[mt][nt], ah[mt], bh0, bh1);
                        mma8(acc[mt][nt], al[mt], bh0, bh1);
                        mma8(acc[mt][nt], ah[mt], bl0, bl1);
                    }
                } else {
                    unsigned bh0 = tf32u(w0), bh1 = tf32u(w1);
                    #pragma unroll
                    for (int mt = 0; mt < 2; mt++) mma8(acc[mt][nt], ah[mt], bh0, bh1);
                }
            }
        }
        __syncthreads();
    }

    float tau = (EPI == 3) ? bias[z] : 0.0f;
    #pragma unroll
    for (int mt = 0; mt < 2; mt++) {
        int gm0 = rowBase + wm * 32 + mt * 16 + lrow;
        int gm1 = gm0 + 8;
        float rd0 = 1.0f, rd1 = 1.0f;
        if (EPI == 4) {
            if (fullTile || gm0 < M) rd0 = 1.0f / aux[(long long)z * M + gm0];
            if (fullTile || gm1 < M) rd1 = 1.0f / aux[(long long)z * M + gm1];
        }
        #pragma unroll
        for (int nt = 0; nt < 8; nt++) {
            int gc = colBase + wn * 64 + nt * 8 + lcol * 2;
            #pragma unroll
            for (int e = 0; e < 4; e++) {
                int gm = (e < 2) ? gm0 : gm1;
                int gn = gc + (e & 1);
                if (!fullTile && (gm >= M || gn >= N)) continue;
                float v = acc[mt][nt][e];
                if (EPI == 1) v += bias[gn];
                else if (EPI == 2) v = fmaxf(v + bias[gn], 0.0f);
                else if (EPI == 3) {
                    float x = (v + 1.0f) * 0.5f;
                    float d = 1.0f - x;
                    v = fmaxf(1.0f - tau * d * d, 0.0f);
                } else if (EPI == 4) v *= (e < 2) ? rd0 : rd1;
                C[(long long)gm * N + gn] = v;
            }
        }
    }
}

constexpr int SMEM_G = (2 * 128 * 36 + 2 * 128 * 36) * 4;  // 73728 B (covers both layouts)

static float* sym(const void* s) {
    void* p = nullptr;
    cudaGetSymbolAddress(&p, s);
    return (float*)p;
}

}  // namespace

extern "C" void kernel_launch(void* const* d_in, const int* in_sizes, int n_in,
                              void* d_out, int out_size) {
    const float* q_in  = (const float*)d_in[0];
    const float* k_in  = (const float*)d_in[1];
    const float* v_in  = (const float*)d_in[2];
    const float* astro = (const float*)d_in[3];
    const float* Wq = (const float*)d_in[4];
    const float* bq = (const float*)d_in[5];
    const float* Wk = (const float*)d_in[6];
    const float* bk = (const float*)d_in[7];
    const float* Wv = (const float*)d_in[8];
    const float* bv = (const float*)d_in[9];
    const float* Wo = (const float*)d_in[10];
    const float* bo = (const float*)d_in[11];
    const float* role_matrix = (const float*)d_in[12];
    const float* Wr1 = (const float*)d_in[13];
    const float* br1 = (const float*)d_in[14];
    const float* Wr2 = (const float*)d_in[15];
    const float* astro_scale = (const float*)d_in[16];
    float* out = (float*)d_out;

    float* CRI    = sym(g_CRI);
    float* IMAT   = sym(g_IMAT);
    float* RoleN  = sym(g_RoleN);
    float* RNspec = sym(g_RNspec);
    float* Q      = sym(g_Q);
    float* Kp     = sym(g_K);
    float* Vp     = sym(g_V);
    float* KB     = sym(g_KB);
    float* H1     = sym(g_H1);
    float* Wt     = sym(g_Wt);
    float* Fr     = sym(g_Fr);
    float* Ka     = sym(g_Ka);
    float* P      = sym(g_P);
    float* S      = sym(g_S);
    float* CTX    = sym(g_CTX);
    float* qnorm  = sym(g_qnorm);
    float* rs     = sym(g_rs);
    float* tau    = sym(g_tau);

    cudaFuncSetAttribute(mma_gemm<0, false, 1>, cudaFuncAttributeMaxDynamicSharedMemorySize, SMEM_G);
    cudaFuncSetAttribute(mma_gemm<1, false, 1>, cudaFuncAttributeMaxDynamicSharedMemorySize, SMEM_G);
    cudaFuncSetAttribute(mma_gemm<1, false, 3>, cudaFuncAttributeMaxDynamicSharedMemorySize, SMEM_G);
    cudaFuncSetAttribute(mma_gemm<2, false, 1>, cudaFuncAttributeMaxDynamicSharedMemorySize, SMEM_G);
    cudaFuncSetAttribute(mma_gemm<3, true,  1>, cudaFuncAttributeMaxDynamicSharedMemorySize, SMEM_G);
    cudaFuncSetAttribute(mma_gemm<4, false, 3>, cudaFuncAttributeMaxDynamicSharedMemorySize, SMEM_G);

    // 1. DFT matrices
    fill_fwd_dft<<<(D_ * W2P_ + 255) / 256, 256>>>();
    fill_inv_dft<<<(W2P_ * D_ + 255) / 256, 256>>>();

    // 2. role rows normalize + spectra
    rownorm_kernel<<<R_, 256>>>(role_matrix, RoleN, nullptr, D_);
    mma_gemm<0, false, 1><<<dim3(9, 1, 1), 256, SMEM_G>>>(
        RoleN, CRI, RNspec, R_, W2P_, D_, 0, 0, 0, nullptr, nullptr);

    // 3. Q, K, V projections (V is on the value path -> x3)
    mma_gemm<1, false, 1><<<dim3(8, 64, 1), 256, SMEM_G>>>(q_in, Wq, Q,  M_, D_, D_, 0, 0, 0, bq, nullptr);
    mma_gemm<1, false, 1><<<dim3(8, 64, 1), 256, SMEM_G>>>(k_in, Wk, Kp, M_, D_, D_, 0, 0, 0, bk, nullptr);
    mma_gemm<1, false, 3><<<dim3(8, 64, 1), 256, SMEM_G>>>(v_in, Wv, Vp, M_, D_, D_, 0, 0, 0, bv, nullptr);

    // 4. surprise + astro state
    rownorm_kernel<<<M_, 256>>>(Q, Q, qnorm, D_);
    astro_kernel<<<B_, 256>>>(qnorm, astro, astro_scale, out + (out_size - B_));

    // 5. role MLP -> softmax weights
    mma_gemm<2, false, 1><<<dim3(4, 64, 1), 256, SMEM_G>>>(Kp, Wr1, H1, M_, H_, D_, 0, 0, 0, br1, nullptr);
    mma_gemm<0, false, 1><<<dim3(1, 64, 1), 256, SMEM_G>>>(H1, Wr2, Wt, M_, R_, H_, 0, 0, 0, nullptr, nullptr);
    softmax64<<<M_ / 8, 256>>>(Wt);

    // 6. holographic binding in frequency domain
    mma_gemm<0, false, 1><<<dim3(9, 64, 1), 256, SMEM_G>>>(
        Wt, RNspec, Fr, M_, W2P_, R_, 0, 0, 0, nullptr, nullptr);
    mma_gemm<0, false, 1><<<dim3(9, 64, 1), 256, SMEM_G>>>(
        Kp, CRI, Ka, M_, W2P_, D_, 0, 0, 0, nullptr, nullptr);
    cmul_kernel<<<(int)(((long long)M_ * NF_ + 255) / 256), 256>>>();
    mma_gemm<0, false, 1><<<dim3(8, 64, 1), 256, SMEM_G>>>(
        P, IMAT, KB, M_, D_, W2P_, 0, 0, 0, nullptr, nullptr);

    // 7. normalize K_bound
    rownorm_kernel<<<M_, 256>>>(KB, KB, nullptr, D_);

    // 8. Epanechnikov scores on cosine sim (x1, as in round 3)
    mma_gemm<3, true, 1><<<dim3(16, 16, B_), 256, SMEM_G>>>(
        Q, KB, S, TQ_, TK_, D_,
        (long long)TQ_ * D_, (long long)TK_ * D_, (long long)TQ_ * TK_, tau, nullptr);

    // 9. denominators, then context = (S @ V) / rowsum   (value path -> x3)
    rowsum_kernel<<<M_, 256>>>(S, rs);
    mma_gemm<4, false, 3><<<dim3(8, 16, B_), 256, SMEM_G>>>(
        S, Vp, CTX, TQ_, D_, TK_,
        (long long)TQ_ * TK_, (long long)TK_ * D_, (long long)TQ_ * D_, nullptr, rs);

    // 10. output projection (value path -> x3)
    mma_gemm<1, false, 3><<<dim3(8, 64, 1), 256, SMEM_G>>>(CTX, Wo, out, M_, D_, D_, 0, 0, 0, bo, nullptr);
}

// round 10
// speedup vs baseline: 2.6142x; 1.3066x over previous
#include <cuda_runtime.h>
#include <math.h>

namespace {

constexpr int B_   = 4;
constexpr int TQ_  = 2048;
constexpr int TK_  = 2048;
constexpr int D_   = 1024;
constexpr int R_   = 64;
constexpr int H_   = 512;
constexpr int NF_  = D_ / 2 + 1;   // 513 rfft bins
constexpr int W2_  = 2 * NF_;      // 1026 (re | im)
constexpr int W2P_ = 1056;         // padded to multiple of BK=32
constexpr int M_   = B_ * TQ_;     // 8192 rows

// ---------------- scratch ----------------------------------------------------
__device__ __align__(128) float g_CRI[D_ * W2P_];
__device__ __align__(128) float g_IMAT[W2P_ * D_];
__device__ __align__(128) float g_RoleN[R_ * D_];
__device__ __align__(128) float g_RNspec[R_ * W2P_];
__device__ __align__(128) float g_Q[M_ * D_];
__device__ __align__(128) float g_K[M_ * D_];
__device__ __align__(128) float g_V[M_ * D_];
__device__ __align__(128) float g_KB[M_ * D_];
__device__ __align__(128) float g_H1[M_ * H_];
__device__ __align__(128) float g_Wt[M_ * R_];
__device__ __align__(128) float g_Fr[(size_t)M_ * W2P_];
__device__ __align__(128) float g_Ka[(size_t)M_ * W2P_];
__device__ __align__(128) float g_P[(size_t)M_ * W2P_];   // pad cols never written -> stay 0
__device__ __align__(128) float g_S[(size_t)B_ * TQ_ * TK_];
__device__ __align__(128) float g_CTX[M_ * D_];
__device__ __align__(128) float g_qnorm[M_];
__device__ __align__(128) float g_rs[M_];
__device__ __align__(128) float g_tau[B_];

// ---------------- DFT matrix fill --------------------------------------------
__global__ void fill_fwd_dft() {
    int idx = blockIdx.x * blockDim.x + threadIdx.x;
    if (idx >= D_ * W2P_) return;
    int d = idx / W2P_, f = idx % W2P_;
    float v = 0.0f;
    if (f < W2_) {
        int fr = (f < NF_) ? f : (f - NF_);
        int m  = (int)(((long long)fr * d) % D_);
        float a = (float)m * (6.283185307179586f / (float)D_);
        v = (f < NF_) ? cosf(a) : -sinf(a);
    }
    g_CRI[idx] = v;
}

__global__ void fill_inv_dft() {
    int idx = blockIdx.x * blockDim.x + threadIdx.x;
    if (idx >= W2P_ * D_) return;
    int f = idx / D_, d = idx % D_;
    float v = 0.0f;
    if (f < W2_) {
        int fr = (f < NF_) ? f : (f - NF_);
        int m  = (int)(((long long)fr * d) % D_);
        float a = (float)m * (6.283185307179586f / (float)D_);
        if (f < NF_) {
            float c = (fr == 0 || fr == D_ / 2) ? 1.0f : 2.0f;
            v = c * cosf(a) * (1.0f / (float)D_);
        } else {
            v = (fr == 0 || fr == D_ / 2) ? 0.0f : (-2.0f / (float)D_) * sinf(a);
        }
    }
    g_IMAT[idx] = v;
}

// ---------------- row l2-normalize -------------------------------------------
__global__ void rownorm_kernel(const float* __restrict__ in, float* __restrict__ out,
                               float* __restrict__ norms, int cols) {
    int row = blockIdx.x;
    const float* p = in + (size_t)row * cols;
    float s = 0.0f;
    for (int c = threadIdx.x; c < cols; c += blockDim.x) { float v = p[c]; s += v * v; }
    __shared__ float red[256];
    red[threadIdx.x] = s;
    __syncthreads();
    for (int o = 128; o > 0; o >>= 1) {
        if (threadIdx.x < o) red[threadIdx.x] += red[threadIdx.x + o];
        __syncthreads();
    }
    float nrm = sqrtf(red[0]);
    if (threadIdx.x == 0 && norms) norms[row] = nrm;
    float inv = 1.0f / fmaxf(nrm, 1e-12f);
    float* q = out + (size_t)row * cols;
    for (int c = threadIdx.x; c < cols; c += blockDim.x) q[c] = p[c] * inv;
}

// ---------------- astrocyte state + tau --------------------------------------
__global__ void astro_kernel(const float* __restrict__ qnorm,
                             const float* __restrict__ astro_in,
                             const float* __restrict__ astro_scale,
                             float* __restrict__ out_state) {
    int b = blockIdx.x;
    float s = 0.0f;
    for (int t = threadIdx.x; t < TQ_; t += blockDim.x) s += qnorm[b * TQ_ + t];
    __shared__ float red[256];
    red[threadIdx.x] = s;
    __syncthreads();
    for (int o = 128; o > 0; o >>= 1) {
        if (threadIdx.x < o) red[threadIdx.x] += red[threadIdx.x + o];
        __syncthreads();
    }
    if (threadIdx.x == 0) {
        float mean_surprise = red[0] / (32.0f * (float)TQ_);
        float ns = 0.95f * astro_in[b] + 0.05f * mean_surprise;
        g_tau[b] = fmaxf(1.0f + astro_scale[0] * ns, 0.001f);
        out_state[b] = ns;
    }
}

// ---------------- softmax over R=64 ------------------------------------------
__global__ void softmax64(float* __restrict__ x) {
    int warp = (blockIdx.x * blockDim.x + threadIdx.x) >> 5;
    int lane = threadIdx.x & 31;
    if (warp >= M_) return;
    float* p = x + (size_t)warp * R_;
    float v0 = p[lane], v1 = p[lane + 32];
    float m = fmaxf(v0, v1);
    #pragma unroll
    for (int o = 16; o > 0; o >>= 1) m = fmaxf(m, __shfl_xor_sync(0xffffffffu, m, o));
    float e0 = expf(v0 - m), e1 = expf(v1 - m);
    float sum = e0 + e1;
    #pragma unroll
    for (int o = 16; o > 0; o >>= 1) sum += __shfl_xor_sync(0xffffffffu, sum, o);
    float inv = 1.0f / sum;
    p[lane] = e0 * inv;
    p[lane + 32] = e1 * inv;
}

// ---------------- complex elementwise product --------------------------------
__global__ void cmul_kernel() {
    long long i = (long long)blockIdx.x * blockDim.x + threadIdx.x;
    if (i >= (long long)M_ * NF_) return;
    long long row = i / NF_;
    int f = (int)(i % NF_);
    const float* a = g_Ka + row * W2P_;
    const float* b = g_Fr + row * W2P_;
    float ar = a[f], ai = a[NF_ + f];
    float br = b[f], bi = b[NF_ + f];
    g_P[row * W2P_ + f]       = ar * br - ai * bi;
    g_P[row * W2P_ + NF_ + f] = ar * bi + ai * br;
}

// ---------------- score row-sum ----------------------------------------------
__global__ void rowsum_kernel(const float* __restrict__ S, float* __restrict__ rs) {
    int row = blockIdx.x;
    const float* p = S + (size_t)row * TK_;
    float s = 0.0f;
    for (int c = threadIdx.x; c < TK_; c += blockDim.x) s += p[c];
    __shared__ float red[256];
    red[threadIdx.x] = s;
    __syncthreads();
    for (int o = 128; o > 0; o >>= 1) {
        if (threadIdx.x < o) red[threadIdx.x] += red[threadIdx.x + o];
        __syncthreads();
    }
    if (threadIdx.x == 0) rs[row] = fmaxf(red[0], 1e-9f);
}

// ---------------- tf32 / cp.async helpers ------------------------------------
__device__ __forceinline__ unsigned tf32u(float x) {
    unsigned u;
    asm("cvt.rna.tf32.f32 %0, %1;" : "=r"(u) : "f"(x));
    return u;
}
__device__ __forceinline__ void cpa16(float* dst, const float* src, int sz) {
    unsigned d = (unsigned)__cvta_generic_to_shared(dst);
    asm volatile("cp.async.cg.shared.global [%0], [%1], 16, %2;" :: "r"(d), "l"(src), "r"(sz));
}
__device__ __forceinline__ void cp_commit() { asm volatile("cp.async.commit_group;"); }
__device__ __forceinline__ void cp_wait0()  { asm volatile("cp.async.wait_group 0;"); }

__device__ __forceinline__ void mma8(float* c, const unsigned* a, unsigned b0, unsigned b1) {
    asm volatile(
        "mma.sync.aligned.m16n8k8.row.col.f32.tf32.tf32.f32 "
        "{%0,%1,%2,%3},{%4,%5,%6,%7},{%8,%9},{%0,%1,%2,%3};"
        : "+f"(c[0]), "+f"(c[1]), "+f"(c[2]), "+f"(c[3])
        : "r"(a[0]), "r"(a[1]), "r"(a[2]), "r"(a[3]), "r"(b0), "r"(b1));
}

// hi = mantissa-truncated value (exact split: v = hi + lo). Raw bits feed tf32 mma.
__device__ __forceinline__ unsigned hibits(float v) { return __float_as_uint(v) & 0xFFFFE000u; }

// ---------------- tf32 tensor-core GEMM v2 (cp.async double-buffered) --------
// C[M,N] = A[M,K] row-major times B (B[K][N] if !TRB, B[N][K] if TRB)
// EPI: 0=none, 1=+bias, 2=relu(+bias), 3=Epanechnikov (bias=tau[z]), 4=/aux[z*M+row]
// PASSES: 1 = single tf32 (cvt.rna, unbiased), 3 = exact hi/lo split x3
template <int EPI, bool TRB, int PASSES>
__global__ void __launch_bounds__(256, 2) mma_gemm(
    const float* __restrict__ Ag, const float* __restrict__ Bg, float* __restrict__ Cg,
    int M, int N, int K, long long sA, long long sB, long long sC,
    const float* __restrict__ bias, const float* __restrict__ aux) {
    constexpr int BM = 128, BN = 128, BK = 32;
    constexpr int AP  = 36;    // row stride (floats) for [row][k] tiles; 144B, 16B-aligned
    constexpr int BPK = 136;   // row stride for [k][n] tile; 544B, 16B-aligned
    constexpr int ASZ = BM * AP;                       // 4608 floats / buffer
    constexpr int BSZ = TRB ? (BN * AP) : (BK * BPK);  // 4608 or 4352
    extern __shared__ float sm[];
    float* As = sm;              // [2][ASZ]
    float* Bs = sm + 2 * ASZ;    // [2][BSZ]

    const int z = blockIdx.z;
    const float* A = Ag + (long long)z * sA;
    const float* B = Bg + (long long)z * sB;
    float* C = Cg + (long long)z * sC;

    const int rowBase = blockIdx.y * BM;
    const int colBase = blockIdx.x * BN;
    const int tid = threadIdx.x;
    const int lane = tid & 31, warp = tid >> 5;
    const int wm = warp >> 1, wn = warp & 1;  // 4 x 2 warp grid
    const int lrow = lane >> 2, lcol = lane & 3;
    const bool fullTile = (rowBase + BM <= M) && (colBase + BN <= N);

    float acc[2][8][4];
    #pragma unroll
    for (int i = 0; i < 2; i++)
        #pragma unroll
        for (int j = 0; j < 8; j++)
            #pragma unroll
            for (int e = 0; e < 4; e++) acc[i][j][e] = 0.0f;

    auto issue = [&](int ch) {
        const int kt = ch * BK;
        float* dA = As + (ch & 1) * ASZ;
        float* dB = Bs + (ch & 1) * BSZ;
        #pragma unroll
        for (int i = 0; i < 4; i++) {        // A: 128 rows x 32 k
            int id = i * 256 + tid;
            int row = id >> 3, c4 = (id & 7) * 4;
            int gm = rowBase + row;
            const float* src = A + (long long)(gm < M ? gm : 0) * K + kt + c4;
            cpa16(dA + row * AP + c4, src, (gm < M) ? 16 : 0);
        }
        if (!TRB) {
            #pragma unroll
            for (int i = 0; i < 4; i++) {    // B: 32 k x 128 n
                int id = i * 256 + tid;
                int k = id >> 5, n4 = (id & 31) * 4;
                int gn = colBase + n4;
                const float* src = B + (long long)(kt + k) * N + (gn < N ? gn : 0);
                cpa16(dB + k * BPK + n4, src, (gn < N) ? 16 : 0);
            }
        } else {
            #pragma unroll
            for (int i = 0; i < 4; i++) {    // B: 128 n-rows x 32 k
                int id = i * 256 + tid;
                int row = id >> 3, c4 = (id & 7) * 4;
                int gn = colBase + row;
                const float* src = B + (long long)(gn < N ? gn : 0) * K + kt + c4;
                cpa16(dB + row * AP + c4, src, (gn < N) ? 16 : 0);
            }
        }
        cp_commit();
    };

    const int nch = K / BK;
    issue(0);
    for (int ch = 0; ch < nch; ch++) {
        cp_wait0();
        __syncthreads();
        if (ch + 1 < nch) issue(ch + 1);
        const float* Ab = As + (ch & 1) * ASZ;
        const float* Bb = Bs + (ch & 1) * BSZ;
        #pragma unroll
        for (int ks = 0; ks < 4; ks++) {
            const int k0 = ks * 8;
            unsigned ah[2][4], al[2][4];
            #pragma unroll
            for (int mt = 0; mt < 2; mt++) {
                const float* ap = Ab + (wm * 32 + mt * 16 + lrow) * AP + k0 + lcol;
                float v0 = ap[0], v1 = ap[8 * AP], v2 = ap[4], v3 = ap[8 * AP + 4];
                if (PASSES == 3) {
                    ah[mt][0] = hibits(v0); ah[mt][1] = hibits(v1);
                    ah[mt][2] = hibits(v2); ah[mt][3] = hibits(v3);
                    al[mt][0] = __float_as_uint(v0 - __uint_as_float(ah[mt][0]));
                    al[mt][1] = __float_as_uint(v1 - __uint_as_float(ah[mt][1]));
                    al[mt][2] = __float_as_uint(v2 - __uint_as_float(ah[mt][2]));
                    al[mt][3] = __float_as_uint(v3 - __uint_as_float(ah[mt][3]));
                } else {
                    ah[mt][0] = tf32u(v0); ah[mt][1] = tf32u(v1);
                    ah[mt][2] = tf32u(v2); ah[mt][3] = tf32u(v3);
                }
            }
            #pragma unroll
            for (int nt = 0; nt < 8; nt++) {
                float w0, w1;
                if (!TRB) {
                    const float* bp = Bb + (k0 + lcol) * BPK + wn * 64 + nt * 8 + lrow;
                    w0 = bp[0]; w1 = bp[4 * BPK];
                } else {
                    const float* bp = Bb + (wn * 64 + nt * 8 + lrow) * AP + k0 + lcol;
                    w0 = bp[0]; w1 = bp[4];
                }
                if (PASSES == 3) {
                    unsigned bh0 = hibits(w0), bh1 = hibits(w1);
                    unsigned bl0 = __float_as_uint(w0 - __uint_as_float(bh0));
                    unsigned bl1 = __float_as_uint(w1 - __uint_as_float(bh1));
                    #pragma unroll
                    for (int mt = 0; mt < 2; mt++) {
                        mma8(acc[mt][nt], ah[mt], bh0, bh1);
                        mma8(acc[mt][nt], al[mt], bh0, bh1);
                        mma8(acc[mt][nt], ah[mt], bl0, bl1);
                    }
                } else {
                    unsigned bh0 = tf32u(w0), bh1 = tf32u(w1);
                    #pragma unroll
                    for (int mt = 0; mt < 2; mt++) mma8(acc[mt][nt], ah[mt], bh0, bh1);
                }
            }
        }
        __syncthreads();
    }

    float tau = (EPI == 3) ? bias[z] : 0.0f;
    #pragma unroll
    for (int mt = 0; mt < 2; mt++) {
        int gm0 = rowBase + wm * 32 + mt * 16 + lrow;
        int gm1 = gm0 + 8;
        float rd0 = 1.0f, rd1 = 1.0f;
        if (EPI == 4) {
            if (fullTile || gm0 < M) rd0 = 1.0f / aux[(long long)z * M + gm0];
            if (fullTile || gm1 < M) rd1 = 1.0f / aux[(long long)z * M + gm1];
        }
        #pragma unroll
        for (int nt = 0; nt < 8; nt++) {
            int gc = colBase + wn * 64 + nt * 8 + lcol * 2;
            #pragma unroll
            for (int e = 0; e < 4; e++) {
                int gm = (e < 2) ? gm0 : gm1;
                int gn = gc + (e & 1);
                if (!fullTile && (gm >= M || gn >= N)) continue;
                float v = acc[mt][nt][e];
                if (EPI == 1) v += bias[gn];
                else if (EPI == 2) v = fmaxf(v + bias[gn], 0.0f);
                else if (EPI == 3) {
                    float x = (v + 1.0f) * 0.5f;
                    float d = 1.0f - x;
                    v = fmaxf(1.0f - tau * d * d, 0.0f);
                } else if (EPI == 4) v *= (e < 2) ? rd0 : rd1;
                C[(long long)gm * N + gn] = v;
            }
        }
    }
}

constexpr int SMEM_G = (2 * 128 * 36 + 2 * 128 * 36) * 4;  // 73728 B (covers both layouts)

static float* sym(const void* s) {
    void* p = nullptr;
    cudaGetSymbolAddress(&p, s);
    return (float*)p;
}

}  // namespace

extern "C" void kernel_launch(void* const* d_in, const int* in_sizes, int n_in,
                              void* d_out, int out_size) {
    const float* q_in  = (const float*)d_in[0];
    const float* k_in  = (const float*)d_in[1];
    const float* v_in  = (const float*)d_in[2];
    const float* astro = (const float*)d_in[3];
    const float* Wq = (const float*)d_in[4];
    const float* bq = (const float*)d_in[5];
    const float* Wk = (const float*)d_in[6];
    const float* bk = (const float*)d_in[7];
    const float* Wv = (const float*)d_in[8];
    const float* bv = (const float*)d_in[9];
    const float* Wo = (const float*)d_in[10];
    const float* bo = (const float*)d_in[11];
    const float* role_matrix = (const float*)d_in[12];
    const float* Wr1 = (const float*)d_in[13];
    const float* br1 = (const float*)d_in[14];
    const float* Wr2 = (const float*)d_in[15];
    const float* astro_scale = (const float*)d_in[16];
    float* out = (float*)d_out;

    float* CRI    = sym(g_CRI);
    float* IMAT   = sym(g_IMAT);
    float* RoleN  = sym(g_RoleN);
    float* RNspec = sym(g_RNspec);
    float* Q      = sym(g_Q);
    float* Kp     = sym(g_K);
    float* Vp     = sym(g_V);
    float* KB     = sym(g_KB);
    float* H1     = sym(g_H1);
    float* Wt     = sym(g_Wt);
    float* Fr     = sym(g_Fr);
    float* Ka     = sym(g_Ka);
    float* P      = sym(g_P);
    float* S      = sym(g_S);
    float* CTX    = sym(g_CTX);
    float* qnorm  = sym(g_qnorm);
    float* rs     = sym(g_rs);
    float* tau    = sym(g_tau);

    cudaFuncSetAttribute(mma_gemm<0, false, 1>, cudaFuncAttributeMaxDynamicSharedMemorySize, SMEM_G);
    cudaFuncSetAttribute(mma_gemm<1, false, 1>, cudaFuncAttributeMaxDynamicSharedMemorySize, SMEM_G);
    cudaFuncSetAttribute(mma_gemm<2, false, 1>, cudaFuncAttributeMaxDynamicSharedMemorySize, SMEM_G);
    cudaFuncSetAttribute(mma_gemm<3, true,  1>, cudaFuncAttributeMaxDynamicSharedMemorySize, SMEM_G);
    cudaFuncSetAttribute(mma_gemm<4, false, 1>, cudaFuncAttributeMaxDynamicSharedMemorySize, SMEM_G);

    // 1. DFT matrices
    fill_fwd_dft<<<(D_ * W2P_ + 255) / 256, 256>>>();
    fill_inv_dft<<<(W2P_ * D_ + 255) / 256, 256>>>();

    // 2. role rows normalize + spectra
    rownorm_kernel<<<R_, 256>>>(role_matrix, RoleN, nullptr, D_);
    mma_gemm<0, false, 1><<<dim3(9, 1, 1), 256, SMEM_G>>>(
        RoleN, CRI, RNspec, R_, W2P_, D_, 0, 0, 0, nullptr, nullptr);

    // 3. Q, K, V projections (all x1 tf32, unbiased rna rounding)
    mma_gemm<1, false, 1><<<dim3(8, 64, 1), 256, SMEM_G>>>(q_in, Wq, Q,  M_, D_, D_, 0, 0, 0, bq, nullptr);
    mma_gemm<1, false, 1><<<dim3(8, 64, 1), 256, SMEM_G>>>(k_in, Wk, Kp, M_, D_, D_, 0, 0, 0, bk, nullptr);
    mma_gemm<1, false, 1><<<dim3(8, 64, 1), 256, SMEM_G>>>(v_in, Wv, Vp, M_, D_, D_, 0, 0, 0, bv, nullptr);

    // 4. surprise + astro state
    rownorm_kernel<<<M_, 256>>>(Q, Q, qnorm, D_);
    astro_kernel<<<B_, 256>>>(qnorm, astro, astro_scale, out + (out_size - B_));

    // 5. role MLP -> softmax weights
    mma_gemm<2, false, 1><<<dim3(4, 64, 1), 256, SMEM_G>>>(Kp, Wr1, H1, M_, H_, D_, 0, 0, 0, br1, nullptr);
    mma_gemm<0, false, 1><<<dim3(1, 64, 1), 256, SMEM_G>>>(H1, Wr2, Wt, M_, R_, H_, 0, 0, 0, nullptr, nullptr);
    softmax64<<<M_ / 8, 256>>>(Wt);

    // 6. holographic binding in frequency domain
    mma_gemm<0, false, 1><<<dim3(9, 64, 1), 256, SMEM_G>>>(
        Wt, RNspec, Fr, M_, W2P_, R_, 0, 0, 0, nullptr, nullptr);
    mma_gemm<0, false, 1><<<dim3(9, 64, 1), 256, SMEM_G>>>(
        Kp, CRI, Ka, M_, W2P_, D_, 0, 0, 0, nullptr, nullptr);
    cmul_kernel<<<(int)(((long long)M_ * NF_ + 255) / 256), 256>>>();
    mma_gemm<0, false, 1><<<dim3(8, 64, 1), 256, SMEM_G>>>(
        P, IMAT, KB, M_, D_, W2P_, 0, 0, 0, nullptr, nullptr);

    // 7. normalize K_bound
    rownorm_kernel<<<M_, 256>>>(KB, KB, nullptr, D_);

    // 8. Epanechnikov scores on cosine sim (x1)
    mma_gemm<3, true, 1><<<dim3(16, 16, B_), 256, SMEM_G>>>(
        Q, KB, S, TQ_, TK_, D_,
        (long long)TQ_ * D_, (long long)TK_ * D_, (long long)TQ_ * TK_, tau, nullptr);

    // 9. denominators, then context = (S @ V) / rowsum   (x1)
    rowsum_kernel<<<M_, 256>>>(S, rs);
    mma_gemm<4, false, 1><<<dim3(8, 16, B_), 256, SMEM_G>>>(
        S, Vp, CTX, TQ_, D_, TK_,
        (long long)TQ_ * TK_, (long long)TK_ * D_, (long long)TQ_ * D_, nullptr, rs);

    // 10. output projection (x1)
    mma_gemm<1, false, 1><<<dim3(8, 64, 1), 256, SMEM_G>>>(CTX, Wo, out, M_, D_, D_, 0, 0, 0, bo, nullptr);
}

// round 12
// speedup vs baseline: 2.7402x; 1.0482x over previous
#include <cuda_runtime.h>
#include <math.h>

namespace {

constexpr int B_   = 4;
constexpr int TQ_  = 2048;
constexpr int TK_  = 2048;
constexpr int D_   = 1024;
constexpr int R_   = 64;
constexpr int H_   = 512;
constexpr int NF_  = D_ / 2 + 1;   // 513 rfft bins
constexpr int W2_  = 2 * NF_;      // 1026 (re | im)
constexpr int W2P_ = 1056;         // padded to multiple of BK=32
constexpr int M_   = B_ * TQ_;     // 8192 rows

// ---------------- scratch ----------------------------------------------------
__device__ __align__(128) float g_CRI[D_ * W2P_];
__device__ __align__(128) float g_IMAT[W2P_ * D_];
__device__ __align__(128) float g_RoleN[R_ * D_];
__device__ __align__(128) float g_RNspec[R_ * W2P_];
__device__ __align__(128) float g_Q[M_ * D_];
__device__ __align__(128) float g_K[M_ * D_];
__device__ __align__(128) float g_V[M_ * D_];
__device__ __align__(128) float g_KB[M_ * D_];
__device__ __align__(128) float g_H1[M_ * H_];
__device__ __align__(128) float g_Wt[M_ * R_];
__device__ __align__(128) float g_Fr[(size_t)M_ * W2P_];
__device__ __align__(128) float g_Ka[(size_t)M_ * W2P_];
__device__ __align__(128) float g_P[(size_t)M_ * W2P_];   // pad cols never written -> stay 0
__device__ __align__(128) float g_S[(size_t)B_ * TQ_ * TK_];
__device__ __align__(128) float g_CTX[M_ * D_];
__device__ __align__(128) float g_qsq[M_];     // Q row sum-of-squares (atomic)
__device__ __align__(128) float g_qnorm[M_];   // |Q row|
__device__ __align__(128) float g_ksq[M_];     // KB row sum-of-squares (atomic)
__device__ __align__(128) float g_invk[M_];    // 1/|KB row|
__device__ __align__(128) float g_rs[M_];      // score row sums (atomic)
__device__ __align__(128) float g_tau[B_];

// ---------------- prep: DFT fills + qsq zero ---------------------------------
constexpr int FN1 = D_ * W2P_;
constexpr int FN2 = W2P_ * D_;
__global__ void prep_fill() {
    int idx = blockIdx.x * blockDim.x + threadIdx.x;
    if (idx < FN1) {                     // CRI[d][f]
        int d = idx / W2P_, f = idx % W2P_;
        float v = 0.0f;
        if (f < W2_) {
            int fr = (f < NF_) ? f : (f - NF_);
            int m  = (int)(((long long)fr * d) % D_);
            float a = (float)m * (6.283185307179586f / (float)D_);
            v = (f < NF_) ? cosf(a) : -sinf(a);
        }
        g_CRI[idx] = v;
    } else if (idx < FN1 + FN2) {        // IMAT[f][d]
        int j = idx - FN1;
        int f = j / D_, d = j % D_;
        float v = 0.0f;
        if (f < W2_) {
            int fr = (f < NF_) ? f : (f - NF_);
            int m  = (int)(((long long)fr * d) % D_);
            float a = (float)m * (6.283185307179586f / (float)D_);
            if (f < NF_) {
                float c = (fr == 0 || fr == D_ / 2) ? 1.0f : 2.0f;
                v = c * cosf(a) * (1.0f / (float)D_);
            } else {
                v = (fr == 0 || fr == D_ / 2) ? 0.0f : (-2.0f / (float)D_) * sinf(a);
            }
        }
        g_IMAT[j] = v;
    } else if (idx < FN1 + FN2 + M_) {
        g_qsq[idx - FN1 - FN2] = 0.0f;
    }
}

// ---------------- role rows: l2-normalize ------------------------------------
__global__ void rownorm_kernel(const float* __restrict__ in, float* __restrict__ out, int cols) {
    int row = blockIdx.x;
    const float* p = in + (size_t)row * cols;
    float s = 0.0f;
    for (int c = threadIdx.x; c < cols; c += blockDim.x) { float v = p[c]; s += v * v; }
    __shared__ float red[256];
    red[threadIdx.x] = s;
    __syncthreads();
    for (int o = 128; o > 0; o >>= 1) {
        if (threadIdx.x < o) red[threadIdx.x] += red[threadIdx.x + o];
        __syncthreads();
    }
    float inv = 1.0f / fmaxf(sqrtf(red[0]), 1e-12f);
    float* q = out + (size_t)row * cols;
    for (int c = threadIdx.x; c < cols; c += blockDim.x) q[c] = p[c] * inv;
}

// ---------------- RNspec = RoleN @ CRI (SIMT thread-per-output) --------------
__global__ void rnspec_kernel() {
    int idx = blockIdx.x * blockDim.x + threadIdx.x;
    if (idx >= R_ * W2P_) return;
    int r = idx / W2P_, w = idx % W2P_;
    const float* rn = g_RoleN + (size_t)r * D_;
    float s = 0.0f;
    #pragma unroll 4
    for (int d = 0; d < D_; d++) s = fmaf(rn[d], g_CRI[(size_t)d * W2P_ + w], s);
    g_RNspec[idx] = s;
}

// ---------------- finalize kernels -------------------------------------------
__global__ void finalize_q() {
    int i = blockIdx.x * blockDim.x + threadIdx.x;
    if (i < M_) g_qnorm[i] = sqrtf(g_qsq[i]);
}
__global__ void finalize_k() {
    int i = blockIdx.x * blockDim.x + threadIdx.x;
    if (i < M_) {
        g_invk[i] = 1.0f / fmaxf(sqrtf(g_ksq[i]), 1e-12f);
        g_rs[i] = 0.0f;
    }
}

// ---------------- astrocyte state + tau --------------------------------------
__global__ void astro_kernel(const float* __restrict__ astro_in,
                             const float* __restrict__ astro_scale,
                             float* __restrict__ out_state) {
    int b = blockIdx.x;
    float s = 0.0f;
    for (int t = threadIdx.x; t < TQ_; t += blockDim.x) s += g_qnorm[b * TQ_ + t];
    __shared__ float red[256];
    red[threadIdx.x] = s;
    __syncthreads();
    for (int o = 128; o > 0; o >>= 1) {
        if (threadIdx.x < o) red[threadIdx.x] += red[threadIdx.x + o];
        __syncthreads();
    }
    if (threadIdx.x == 0) {
        float mean_surprise = red[0] / (32.0f * (float)TQ_);
        float ns = 0.95f * astro_in[b] + 0.05f * mean_surprise;
        g_tau[b] = fmaxf(1.0f + astro_scale[0] * ns, 0.001f);
        out_state[b] = ns;
    }
}

// ---------------- softmax over R=64 ------------------------------------------
__global__ void softmax64(float* __restrict__ x) {
    int warp = (blockIdx.x * blockDim.x + threadIdx.x) >> 5;
    int lane = threadIdx.x & 31;
    if (warp >= M_) return;
    float* p = x + (size_t)warp * R_;
    float v0 = p[lane], v1 = p[lane + 32];
    float m = fmaxf(v0, v1);
    #pragma unroll
    for (int o = 16; o > 0; o >>= 1) m = fmaxf(m, __shfl_xor_sync(0xffffffffu, m, o));
    float e0 = expf(v0 - m), e1 = expf(v1 - m);
    float sum = e0 + e1;
    #pragma unroll
    for (int o = 16; o > 0; o >>= 1) sum += __shfl_xor_sync(0xffffffffu, sum, o);
    float inv = 1.0f / sum;
    p[lane] = e0 * inv;
    p[lane + 32] = e1 * inv;
}

// ---------------- complex elementwise product (+ ksq zero) -------------------
__global__ void cmul_kernel() {
    long long i = (long long)blockIdx.x * blockDim.x + threadIdx.x;
    if (i >= (long long)M_ * NF_) return;
    if (i < M_) g_ksq[i] = 0.0f;
    long long row = i / NF_;
    int f = (int)(i % NF_);
    const float* a = g_Ka + row * W2P_;
    const float* b = g_Fr + row * W2P_;
    float ar = a[f], ai = a[NF_ + f];
    float br = b[f], bi = b[NF_ + f];
    g_P[row * W2P_ + f]       = ar * br - ai * bi;
    g_P[row * W2P_ + NF_ + f] = ar * bi + ai * br;
}

// ---------------- tf32 / cp.async helpers ------------------------------------
__device__ __forceinline__ unsigned tf32u(float x) {
    unsigned u;
    asm("cvt.rna.tf32.f32 %0, %1;" : "=r"(u) : "f"(x));
    return u;
}
__device__ __forceinline__ void cpa16(float* dst, const float* src, int sz) {
    unsigned d = (unsigned)__cvta_generic_to_shared(dst);
    asm volatile("cp.async.cg.shared.global [%0], [%1], 16, %2;" :: "r"(d), "l"(src), "r"(sz));
}
__device__ __forceinline__ void cp_commit() { asm volatile("cp.async.commit_group;"); }
__device__ __forceinline__ void cp_wait0()  { asm volatile("cp.async.wait_group 0;"); }

__device__ __forceinline__ void mma8(float* c, const unsigned* a, unsigned b0, unsigned b1) {
    asm volatile(
        "mma.sync.aligned.m16n8k8.row.col.f32.tf32.tf32.f32 "
        "{%0,%1,%2,%3},{%4,%5,%6,%7},{%8,%9},{%0,%1,%2,%3};"
        : "+f"(c[0]), "+f"(c[1]), "+f"(c[2]), "+f"(c[3])
        : "r"(a[0]), "r"(a[1]), "r"(a[2]), "r"(a[3]), "r"(b0), "r"(b1));
}

// ---------------- tf32 GEMM body (cp.async double-buffered) ------------------
// C[M,N] = A[M,K] row-major times B (B[K][N] if !TRB, B[N][K] if TRB)
// EPI: 0=none, 1=+bias, 2=relu(+bias),
//      3=scores: tau=bias[z], aux=|q| row, aux2=1/|k| col, rsum += row sums
//      4=divide by max(aux[z*M+row],1e-9)
//      6=+bias, rsum += row sum-of-squares (full tiles)
//      7=none,  rsum += row sum-of-squares (full tiles)
template <int EPI, bool TRB>
__device__ __forceinline__ void gemm_body(
    const float* __restrict__ A, const float* __restrict__ B, float* __restrict__ C,
    int M, int N, int K, int rowBase, int colBase, int z,
    const float* __restrict__ bias, const float* __restrict__ aux,
    const float* __restrict__ aux2, float* __restrict__ rsum) {
    constexpr int BM = 128, BN = 128, BK = 32;
    constexpr int AP  = 36;
    constexpr int BPK = 136;
    constexpr int ASZ = BM * AP;
    constexpr int BSZ = TRB ? (BN * AP) : (BK * BPK);
    extern __shared__ float sm[];
    float* As = sm;
    float* Bs = sm + 2 * ASZ;

    const int tid = threadIdx.x;
    const int lane = tid & 31, warp = tid >> 5;
    const int wm = warp >> 1, wn = warp & 1;
    const int lrow = lane >> 2, lcol = lane & 3;
    const bool fullTile = (rowBase + BM <= M) && (colBase + BN <= N);

    float acc[2][8][4];
    #pragma unroll
    for (int i = 0; i < 2; i++)
        #pragma unroll
        for (int j = 0; j < 8; j++)
            #pragma unroll
            for (int e = 0; e < 4; e++) acc[i][j][e] = 0.0f;

    auto issue = [&](int ch) {
        const int kt = ch * BK;
        float* dA = As + (ch & 1) * ASZ;
        float* dB = Bs + (ch & 1) * BSZ;
        #pragma unroll
        for (int i = 0; i < 4; i++) {
            int id = i * 256 + tid;
            int row = id >> 3, c4 = (id & 7) * 4;
            int gm = rowBase + row;
            const float* src = A + (long long)(gm < M ? gm : 0) * K + kt + c4;
            cpa16(dA + row * AP + c4, src, (gm < M) ? 16 : 0);
        }
        if (!TRB) {
            #pragma unroll
            for (int i = 0; i < 4; i++) {
                int id = i * 256 + tid;
                int k = id >> 5, n4 = (id & 31) * 4;
                int gn = colBase + n4;
                const float* src = B + (long long)(kt + k) * N + (gn < N ? gn : 0);
                cpa16(dB + k * BPK + n4, src, (gn < N) ? 16 : 0);
            }
        } else {
            #pragma unroll
            for (int i = 0; i < 4; i++) {
                int id = i * 256 + tid;
                int row = id >> 3, c4 = (id & 7) * 4;
                int gn = colBase + row;
                const float* src = B + (long long)(gn < N ? gn : 0) * K + kt + c4;
                cpa16(dB + row * AP + c4, src, (gn < N) ? 16 : 0);
            }
        }
        cp_commit();
    };

    const int nch = K / BK;
    issue(0);
    for (int ch = 0; ch < nch; ch++) {
        cp_wait0();
        __syncthreads();
        if (ch + 1 < nch) issue(ch + 1);
        const float* Ab = As + (ch & 1) * ASZ;
        const float* Bb = Bs + (ch & 1) * BSZ;
        #pragma unroll
        for (int ks = 0; ks < 4; ks++) {
            const int k0 = ks * 8;
            unsigned ah[2][4];
            #pragma unroll
            for (int mt = 0; mt < 2; mt++) {
                const float* ap = Ab + (wm * 32 + mt * 16 + lrow) * AP + k0 + lcol;
                ah[mt][0] = tf32u(ap[0]);
                ah[mt][1] = tf32u(ap[8 * AP]);
                ah[mt][2] = tf32u(ap[4]);
                ah[mt][3] = tf32u(ap[8 * AP + 4]);
            }
            #pragma unroll
            for (int nt = 0; nt < 8; nt++) {
                float w0, w1;
                if (!TRB) {
                    const float* bp = Bb + (k0 + lcol) * BPK + wn * 64 + nt * 8 + lrow;
                    w0 = bp[0]; w1 = bp[4 * BPK];
                } else {
                    const float* bp = Bb + (wn * 64 + nt * 8 + lrow) * AP + k0 + lcol;
                    w0 = bp[0]; w1 = bp[4];
                }
                unsigned bh0 = tf32u(w0), bh1 = tf32u(w1);
                #pragma unroll
                for (int mt = 0; mt < 2; mt++) mma8(acc[mt][nt], ah[mt], bh0, bh1);
            }
        }
        __syncthreads();
    }

    if (EPI == 3) {
        // scores: cosine normalization + Epanechnikov + fused rowsum (full tiles)
        const float tau = bias[z];
        #pragma unroll
        for (int mt = 0; mt < 2; mt++) {
            int gm0 = rowBase + wm * 32 + mt * 16 + lrow;
            int gm1 = gm0 + 8;
            float rq0 = 1.0f / fmaxf(aux[(long long)z * M + gm0], 1e-12f);
            float rq1 = 1.0f / fmaxf(aux[(long long)z * M + gm1], 1e-12f);
            float sum0 = 0.0f, sum1 = 0.0f;
            #pragma unroll
            for (int nt = 0; nt < 8; nt++) {
                int gc = colBase + wn * 64 + nt * 8 + lcol * 2;
                float ck0 = aux2[(long long)z * N + gc];
                float ck1 = aux2[(long long)z * N + gc + 1];
                #pragma unroll
                for (int e = 0; e < 4; e++) {
                    int gm = (e < 2) ? gm0 : gm1;
                    int gn = gc + (e & 1);
                    float x = acc[mt][nt][e] * ((e < 2) ? rq0 : rq1) * ((e & 1) ? ck1 : ck0);
                    x = (x + 1.0f) * 0.5f;
                    float dd = 1.0f - x;
                    float v = fmaxf(1.0f - tau * dd * dd, 0.0f);
                    C[(long long)gm * N + gn] = v;
                    if (e < 2) sum0 += v; else sum1 += v;
                }
            }
            sum0 += __shfl_xor_sync(0xffffffffu, sum0, 1);
            sum0 += __shfl_xor_sync(0xffffffffu, sum0, 2);
            sum1 += __shfl_xor_sync(0xffffffffu, sum1, 1);
            sum1 += __shfl_xor_sync(0xffffffffu, sum1, 2);
            if (lcol == 0) {
                atomicAdd(&rsum[(long long)z * M + gm0], sum0);
                atomicAdd(&rsum[(long long)z * M + gm1], sum1);
            }
        }
        return;
    }

    if (EPI == 6 || EPI == 7) {
        // projection + fused row sum-of-squares (full tiles: M,N 128-divisible)
        #pragma unroll
        for (int mt = 0; mt < 2; mt++) {
            int gm0 = rowBase + wm * 32 + mt * 16 + lrow;
            int gm1 = gm0 + 8;
            float sum0 = 0.0f, sum1 = 0.0f;
            #pragma unroll
            for (int nt = 0; nt < 8; nt++) {
                int gc = colBase + wn * 64 + nt * 8 + lcol * 2;
                #pragma unroll
                for (int e = 0; e < 4; e++) {
                    int gm = (e < 2) ? gm0 : gm1;
                    int gn = gc + (e & 1);
                    float v = acc[mt][nt][e];
                    if (EPI == 6) v += bias[gn];
                    C[(long long)gm * N + gn] = v;
                    if (e < 2) sum0 += v * v; else sum1 += v * v;
                }
            }
            sum0 += __shfl_xor_sync(0xffffffffu, sum0, 1);
            sum0 += __shfl_xor_sync(0xffffffffu, sum0, 2);
            sum1 += __shfl_xor_sync(0xffffffffu, sum1, 1);
            sum1 += __shfl_xor_sync(0xffffffffu, sum1, 2);
            if (lcol == 0) {
                atomicAdd(&rsum[gm0], sum0);
                atomicAdd(&rsum[gm1], sum1);
            }
        }
        return;
    }

    #pragma unroll
    for (int mt = 0; mt < 2; mt++) {
        int gm0 = rowBase + wm * 32 + mt * 16 + lrow;
        int gm1 = gm0 + 8;
        float rd0 = 1.0f, rd1 = 1.0f;
        if (EPI == 4) {
            if (fullTile || gm0 < M) rd0 = 1.0f / fmaxf(aux[(long long)z * M + gm0], 1e-9f);
            if (fullTile || gm1 < M) rd1 = 1.0f / fmaxf(aux[(long long)z * M + gm1], 1e-9f);
        }
        #pragma unroll
        for (int nt = 0; nt < 8; nt++) {
            int gc = colBase + wn * 64 + nt * 8 + lcol * 2;
            #pragma unroll
            for (int e = 0; e < 4; e++) {
                int gm = (e < 2) ? gm0 : gm1;
                int gn = gc + (e & 1);
                if (!fullTile && (gm >= M || gn >= N)) continue;
                float v = acc[mt][nt][e];
                if (EPI == 1) v += bias[gn];
                else if (EPI == 2) v = fmaxf(v + bias[gn], 0.0f);
                else if (EPI == 4) v *= (e < 2) ? rd0 : rd1;
                C[(long long)gm * N + gn] = v;
            }
        }
    }
}

// ---------------- global wrappers --------------------------------------------
template <int EPI, bool TRB>
__global__ void __launch_bounds__(256, 2) mma_gemm(
    const float* __restrict__ Ag, const float* __restrict__ Bg, float* __restrict__ Cg,
    int M, int N, int K, long long sA, long long sB, long long sC,
    const float* __restrict__ bias, const float* __restrict__ aux,
    const float* __restrict__ aux2, float* __restrict__ rsum) {
    const int z = blockIdx.z;
    gemm_body<EPI, TRB>(Ag + (long long)z * sA, Bg + (long long)z * sB,
                        Cg + (long long)z * sC, M, N, K,
                        blockIdx.y * 128, blockIdx.x * 128, z, bias, aux, aux2, rsum);
}

struct QKVArgs {
    const float* A[3];
    const float* Bm[3];
    float* C[3];
    const float* bias[3];
    float* qsq;
};
// z=0: Q projection (+bias, fused row sumsq); z=1: K, z=2: V (+bias only)
__global__ void __launch_bounds__(256, 2) qkv_gemm(QKVArgs p) {
    const int z = blockIdx.z;
    const int rb = blockIdx.y * 128, cb = blockIdx.x * 128;
    if (z == 0)
        gemm_body<6, false>(p.A[0], p.Bm[0], p.C[0], M_, D_, D_, rb, cb, 0,
                            p.bias[0], nullptr, nullptr, p.qsq);
    else if (z == 1)
        gemm_body<1, false>(p.A[1], p.Bm[1], p.C[1], M_, D_, D_, rb, cb, 0,
                            p.bias[1], nullptr, nullptr, nullptr);
    else
        gemm_body<1, false>(p.A[2], p.Bm[2], p.C[2], M_, D_, D_, rb, cb, 0,
                            p.bias[2], nullptr, nullptr, nullptr);
}

// blockIdx.x < 4: H1 = relu(K@Wr1+br1);  x >= 4: Ka = K @ CRI
__global__ void __launch_bounds__(256, 2) h1ka_gemm(
    const float* __restrict__ Kp, const float* __restrict__ Wr1,
    const float* __restrict__ br1, float* __restrict__ H1,
    const float* __restrict__ CRI, float* __restrict__ Ka) {
    const int rb = blockIdx.y * 128;
    if (blockIdx.x < 4)
        gemm_body<2, false>(Kp, Wr1, H1, M_, H_, D_, rb, blockIdx.x * 128, 0,
                            br1, nullptr, nullptr, nullptr);
    else
        gemm_body<0, false>(Kp, CRI, Ka, M_, W2P_, D_, rb, (blockIdx.x - 4) * 128, 0,
                            nullptr, nullptr, nullptr, nullptr);
}

constexpr int SMEM_G = (2 * 128 * 36 + 2 * 128 * 36) * 4;  // 73728 B

static float* sym(const void* s) {
    void* p = nullptr;
    cudaGetSymbolAddress(&p, s);
    return (float*)p;
}

}  // namespace

extern "C" void kernel_launch(void* const* d_in, const int* in_sizes, int n_in,
                              void* d_out, int out_size) {
    const float* q_in  = (const float*)d_in[0];
    const float* k_in  = (const float*)d_in[1];
    const float* v_in  = (const float*)d_in[2];
    const float* astro = (const float*)d_in[3];
    const float* Wq = (const float*)d_in[4];
    const float* bq = (const float*)d_in[5];
    const float* Wk = (const float*)d_in[6];
    const float* bk = (const float*)d_in[7];
    const float* Wv = (const float*)d_in[8];
    const float* bv = (const float*)d_in[9];
    const float* Wo = (const float*)d_in[10];
    const float* bo = (const float*)d_in[11];
    const float* role_matrix = (const float*)d_in[12];
    const float* Wr1 = (const float*)d_in[13];
    const float* br1 = (const float*)d_in[14];
    const float* Wr2 = (const float*)d_in[15];
    const float* astro_scale = (const float*)d_in[16];
    float* out = (float*)d_out;

    float* RoleN  = sym(g_RoleN);
    float* Q      = sym(g_Q);
    float* Kp     = sym(g_K);
    float* Vp     = sym(g_V);
    float* KB     = sym(g_KB);
    float* H1     = sym(g_H1);
    float* Wt     = sym(g_Wt);
    float* Fr     = sym(g_Fr);
    float* Ka     = sym(g_Ka);
    float* P      = sym(g_P);
    float* S      = sym(g_S);
    float* CTX    = sym(g_CTX);
    float* CRI    = sym(g_CRI);
    float* IMAT   = sym(g_IMAT);
    float* RNspec = sym(g_RNspec);
    float* qsq    = sym(g_qsq);
    float* qnorm  = sym(g_qnorm);
    float* ksq    = sym(g_ksq);
    float* invk   = sym(g_invk);
    float* rs     = sym(g_rs);
    float* tau    = sym(g_tau);

    cudaFuncSetAttribute(mma_gemm<0, false>, cudaFuncAttributeMaxDynamicSharedMemorySize, SMEM_G);
    cudaFuncSetAttribute(mma_gemm<1, false>, cudaFuncAttributeMaxDynamicSharedMemorySize, SMEM_G);
    cudaFuncSetAttribute(mma_gemm<3, true >, cudaFuncAttributeMaxDynamicSharedMemorySize, SMEM_G);
    cudaFuncSetAttribute(mma_gemm<4, false>, cudaFuncAttributeMaxDynamicSharedMemorySize, SMEM_G);
    cudaFuncSetAttribute(mma_gemm<7, false>, cudaFuncAttributeMaxDynamicSharedMemorySize, SMEM_G);
    cudaFuncSetAttribute(qkv_gemm,  cudaFuncAttributeMaxDynamicSharedMemorySize, SMEM_G);
    cudaFuncSetAttribute(h1ka_gemm, cudaFuncAttributeMaxDynamicSharedMemorySize, SMEM_G);

    // 1. DFT matrices + qsq zeroing (one kernel)
    prep_fill<<<(FN1 + FN2 + M_ + 255) / 256, 256>>>();

    // 2. role rows normalize + spectra (SIMT)
    rownorm_kernel<<<R_, 256>>>(role_matrix, RoleN, D_);
    rnspec_kernel<<<(R_ * W2P_ + 255) / 256, 256>>>();

    // 3. Q, K, V projections in ONE launch (Q fuses row sum-of-squares)
    QKVArgs qa;
    qa.A[0] = q_in; qa.A[1] = k_in; qa.A[2] = v_in;
    qa.Bm[0] = Wq;  qa.Bm[1] = Wk;  qa.Bm[2] = Wv;
    qa.C[0] = Q;    qa.C[1] = Kp;   qa.C[2] = Vp;
    qa.bias[0] = bq; qa.bias[1] = bk; qa.bias[2] = bv;
    qa.qsq = qsq;
    qkv_gemm<<<dim3(8, 64, 3), 256, SMEM_G>>>(qa);

    // 4. |Q| rows; astro state + tau
    finalize_q<<<(M_ + 255) / 256, 256>>>();
    astro_kernel<<<B_, 256>>>(astro, astro_scale, out + (out_size - B_));

    // 5. H1 (role MLP layer 1) + Ka (K spectra) in ONE launch
    h1ka_gemm<<<dim3(13, 64, 1), 256, SMEM_G>>>(Kp, Wr1, br1, H1, CRI, Ka);

    // 6. role logits -> softmax weights -> Fr spectra
    mma_gemm<0, false><<<dim3(1, 64, 1), 256, SMEM_G>>>(
        H1, Wr2, Wt, M_, R_, H_, 0, 0, 0, nullptr, nullptr, nullptr, nullptr);
    softmax64<<<M_ / 8, 256>>>(Wt);
    mma_gemm<0, false><<<dim3(9, 64, 1), 256, SMEM_G>>>(
        Wt, RNspec, Fr, M_, W2P_, R_, 0, 0, 0, nullptr, nullptr, nullptr, nullptr);

    // 7. binding product (also zeroes ksq), inverse DFT (fuses |KB| sumsq)
    cmul_kernel<<<(int)(((long long)M_ * NF_ + 255) / 256), 256>>>();
    mma_gemm<7, false><<<dim3(8, 64, 1), 256, SMEM_G>>>(
        P, IMAT, KB, M_, D_, W2P_, 0, 0, 0, nullptr, nullptr, nullptr, ksq);
    finalize_k<<<(M_ + 255) / 256, 256>>>();

    // 8. scores: fused cosine normalization + Epanechnikov + rowsum
    mma_gemm<3, true><<<dim3(16, 16, B_), 256, SMEM_G>>>(
        Q, KB, S, TQ_, TK_, D_,
        (long long)TQ_ * D_, (long long)TK_ * D_, (long long)TQ_ * TK_,
        tau, qnorm, invk, rs);

    // 9. context = (S @ V) / rowsum, then output projection
    mma_gemm<4, false><<<dim3(8, 16, B_), 256, SMEM_G>>>(
        S, Vp, CTX, TQ_, D_, TK_,
        (long long)TQ_ * TK_, (long long)TK_ * D_, (long long)TQ_ * D_,
        nullptr, rs, nullptr, nullptr);
    mma_gemm<1, false><<<dim3(8, 64, 1), 256, SMEM_G>>>(
        CTX, Wo, out, M_, D_, D_, 0, 0, 0, bo, nullptr, nullptr, nullptr);
}

// round 13
// speedup vs baseline: 3.0695x; 1.1202x over previous
#include <cuda_runtime.h>
#include <math.h>

namespace {

constexpr int B_   = 4;
constexpr int TQ_  = 2048;
constexpr int TK_  = 2048;
constexpr int D_   = 1024;
constexpr int R_   = 64;
constexpr int H_   = 512;
constexpr int NF_  = D_ / 2 + 1;   // 513 rfft bins
constexpr int W2_  = 2 * NF_;      // 1026 (re | im)
constexpr int W2P_ = 1056;         // padded to multiple of BK=32
constexpr int M_   = B_ * TQ_;     // 8192 rows
constexpr size_t MD = (size_t)M_ * D_;
constexpr size_t DD = (size_t)D_ * D_;
constexpr size_t DH = (size_t)D_ * H_;
constexpr size_t HR = (size_t)H_ * R_;

// ---------------- scratch ----------------------------------------------------
__device__ __align__(128) float g_CRI[D_ * W2P_];
__device__ __align__(128) float g_IMAT[W2P_ * D_];
__device__ __align__(128) float g_RoleN[R_ * D_];
__device__ __align__(128) float g_RNspec[R_ * W2P_];
__device__ __align__(128) float g_Q[MD];
__device__ __align__(128) float g_K[MD];
__device__ __align__(128) float g_V[MD];
__device__ __align__(128) float g_KB[MD];
__device__ __align__(128) float g_H1[M_ * H_];
__device__ __align__(128) float g_Wt[M_ * R_];
__device__ __align__(128) float g_Fr[(size_t)M_ * W2P_];
__device__ __align__(128) float g_Ka[(size_t)M_ * W2P_];
__device__ __align__(128) float g_P[(size_t)M_ * W2P_];   // pad cols never written -> stay 0
__device__ __align__(128) float g_S[(size_t)B_ * TQ_ * TK_];
__device__ __align__(128) float g_CTX[MD];
// tf32-pre-rounded copies of external inputs
__device__ __align__(128) float g_QI[MD];
__device__ __align__(128) float g_KI[MD];
__device__ __align__(128) float g_VI[MD];
__device__ __align__(128) float g_Wqr[DD];
__device__ __align__(128) float g_Wkr[DD];
__device__ __align__(128) float g_Wvr[DD];
__device__ __align__(128) float g_Wor[DD];
__device__ __align__(128) float g_W1r[DH];
__device__ __align__(128) float g_W2r[HR];
__device__ __align__(128) float g_qsq[M_];
__device__ __align__(128) float g_qnorm[M_];
__device__ __align__(128) float g_ksq[M_];
__device__ __align__(128) float g_invk[M_];
__device__ __align__(128) float g_rs[M_];
__device__ __align__(128) float g_tau[B_];

// ---------------- tf32 rounding helpers ---------------------------------------
__device__ __forceinline__ unsigned tf32u(float x) {
    unsigned u;
    asm("cvt.rna.tf32.f32 %0, %1;" : "=r"(u) : "f"(x));
    return u;
}
__device__ __forceinline__ float rnd(float v) { return __uint_as_float(tf32u(v)); }

// ---------------- prep: DFT fills (tf32-rounded) + qsq zero ------------------
constexpr int FN1 = D_ * W2P_;
constexpr int FN2 = W2P_ * D_;
__global__ void prep_fill() {
    int idx = blockIdx.x * blockDim.x + threadIdx.x;
    if (idx < FN1) {                     // CRI[d][f]
        int d = idx / W2P_, f = idx % W2P_;
        float v = 0.0f;
        if (f < W2_) {
            int fr = (f < NF_) ? f : (f - NF_);
            int m  = (int)(((long long)fr * d) % D_);
            float a = (float)m * (6.283185307179586f / (float)D_);
            v = (f < NF_) ? cosf(a) : -sinf(a);
        }
        g_CRI[idx] = rnd(v);
    } else if (idx < FN1 + FN2) {        // IMAT[f][d]
        int j = idx - FN1;
        int f = j / D_, d = j % D_;
        float v = 0.0f;
        if (f < W2_) {
            int fr = (f < NF_) ? f : (f - NF_);
            int m  = (int)(((long long)fr * d) % D_);
            float a = (float)m * (6.283185307179586f / (float)D_);
            if (f < NF_) {
                float c = (fr == 0 || fr == D_ / 2) ? 1.0f : 2.0f;
                v = c * cosf(a) * (1.0f / (float)D_);
            } else {
                v = (fr == 0 || fr == D_ / 2) ? 0.0f : (-2.0f / (float)D_) * sinf(a);
            }
        }
        g_IMAT[j] = rnd(v);
    } else if (idx < FN1 + FN2 + M_) {
        g_qsq[idx - FN1 - FN2] = 0.0f;
    }
}

// ---------------- pre-round external inputs (vectorized) ---------------------
struct RoundArgs {
    const float4* in[9];
    float4* out[9];
    long long end4[9];   // cumulative end (in float4 units)
};
__global__ void round_inputs(RoundArgs ra) {
    long long i = (long long)blockIdx.x * blockDim.x + threadIdx.x;
    if (i >= ra.end4[8]) return;
    int s = 0;
    while (i >= ra.end4[s]) s++;
    long long base = (s == 0) ? 0 : ra.end4[s - 1];
    long long j = i - base;
    float4 v = ra.in[s][j];
    v.x = rnd(v.x); v.y = rnd(v.y); v.z = rnd(v.z); v.w = rnd(v.w);
    ra.out[s][j] = v;
}

// ---------------- role rows: l2-normalize ------------------------------------
__global__ void rownorm_kernel(const float* __restrict__ in, float* __restrict__ out, int cols) {
    int row = blockIdx.x;
    const float* p = in + (size_t)row * cols;
    float s = 0.0f;
    for (int c = threadIdx.x; c < cols; c += blockDim.x) { float v = p[c]; s += v * v; }
    __shared__ float red[256];
    red[threadIdx.x] = s;
    __syncthreads();
    for (int o = 128; o > 0; o >>= 1) {
        if (threadIdx.x < o) red[threadIdx.x] += red[threadIdx.x + o];
        __syncthreads();
    }
    float inv = 1.0f / fmaxf(sqrtf(red[0]), 1e-12f);
    float* q = out + (size_t)row * cols;
    for (int c = threadIdx.x; c < cols; c += blockDim.x) q[c] = p[c] * inv;
}

// ---------------- RNspec = RoleN @ CRI (SIMT, rounded store) -----------------
__global__ void rnspec_kernel() {
    int idx = blockIdx.x * blockDim.x + threadIdx.x;
    if (idx >= R_ * W2P_) return;
    int r = idx / W2P_, w = idx % W2P_;
    const float* rn = g_RoleN + (size_t)r * D_;
    float s = 0.0f;
    #pragma unroll 4
    for (int d = 0; d < D_; d++) s = fmaf(rn[d], g_CRI[(size_t)d * W2P_ + w], s);
    g_RNspec[idx] = rnd(s);
}

// ---------------- finalize kernels -------------------------------------------
__global__ void finalize_q() {
    int i = blockIdx.x * blockDim.x + threadIdx.x;
    if (i < M_) g_qnorm[i] = sqrtf(g_qsq[i]);
}
__global__ void finalize_k() {
    int i = blockIdx.x * blockDim.x + threadIdx.x;
    if (i < M_) {
        g_invk[i] = 1.0f / fmaxf(sqrtf(g_ksq[i]), 1e-12f);
        g_rs[i] = 0.0f;
    }
}

// ---------------- astrocyte state + tau --------------------------------------
__global__ void astro_kernel(const float* __restrict__ astro_in,
                             const float* __restrict__ astro_scale,
                             float* __restrict__ out_state) {
    int b = blockIdx.x;
    float s = 0.0f;
    for (int t = threadIdx.x; t < TQ_; t += blockDim.x) s += g_qnorm[b * TQ_ + t];
    __shared__ float red[256];
    red[threadIdx.x] = s;
    __syncthreads();
    for (int o = 128; o > 0; o >>= 1) {
        if (threadIdx.x < o) red[threadIdx.x] += red[threadIdx.x + o];
        __syncthreads();
    }
    if (threadIdx.x == 0) {
        float mean_surprise = red[0] / (32.0f * (float)TQ_);
        float ns = 0.95f * astro_in[b] + 0.05f * mean_surprise;
        g_tau[b] = fmaxf(1.0f + astro_scale[0] * ns, 0.001f);
        out_state[b] = ns;
    }
}

// ---------------- softmax over R=64 (rounded stores) -------------------------
__global__ void softmax64(float* __restrict__ x) {
    int warp = (blockIdx.x * blockDim.x + threadIdx.x) >> 5;
    int lane = threadIdx.x & 31;
    if (warp >= M_) return;
    float* p = x + (size_t)warp * R_;
    float v0 = p[lane], v1 = p[lane + 32];
    float m = fmaxf(v0, v1);
    #pragma unroll
    for (int o = 16; o > 0; o >>= 1) m = fmaxf(m, __shfl_xor_sync(0xffffffffu, m, o));
    float e0 = expf(v0 - m), e1 = expf(v1 - m);
    float sum = e0 + e1;
    #pragma unroll
    for (int o = 16; o > 0; o >>= 1) sum += __shfl_xor_sync(0xffffffffu, sum, o);
    float inv = 1.0f / sum;
    p[lane] = rnd(e0 * inv);
    p[lane + 32] = rnd(e1 * inv);
}

// ---------------- complex product (rounded stores; + ksq zero) ---------------
__global__ void cmul_kernel() {
    long long i = (long long)blockIdx.x * blockDim.x + threadIdx.x;
    if (i >= (long long)M_ * NF_) return;
    if (i < M_) g_ksq[i] = 0.0f;
    long long row = i / NF_;
    int f = (int)(i % NF_);
    const float* a = g_Ka + row * W2P_;
    const float* b = g_Fr + row * W2P_;
    float ar = a[f], ai = a[NF_ + f];
    float br = b[f], bi = b[NF_ + f];
    g_P[row * W2P_ + f]       = rnd(ar * br - ai * bi);
    g_P[row * W2P_ + NF_ + f] = rnd(ar * bi + ai * br);
}

// ---------------- cp.async helpers -------------------------------------------
__device__ __forceinline__ void cpa16(float* dst, const float* src, int sz) {
    unsigned d = (unsigned)__cvta_generic_to_shared(dst);
    asm volatile("cp.async.cg.shared.global [%0], [%1], 16, %2;" :: "r"(d), "l"(src), "r"(sz));
}
__device__ __forceinline__ void cp_commit() { asm volatile("cp.async.commit_group;"); }
__device__ __forceinline__ void cp_wait0()  { asm volatile("cp.async.wait_group 0;"); }

__device__ __forceinline__ void mma8(float* c, const unsigned* a, unsigned b0, unsigned b1) {
    asm volatile(
        "mma.sync.aligned.m16n8k8.row.col.f32.tf32.tf32.f32 "
        "{%0,%1,%2,%3},{%4,%5,%6,%7},{%8,%9},{%0,%1,%2,%3};"
        : "+f"(c[0]), "+f"(c[1]), "+f"(c[2]), "+f"(c[3])
        : "r"(a[0]), "r"(a[1]), "r"(a[2]), "r"(a[3]), "r"(b0), "r"(b1));
}

// ---------------- tf32 GEMM body (operands pre-rounded; no inner cvt) --------
// C[M,N] = A[M,K] row-major times B (B[K][N] if !TRB, B[N][K] if TRB)
// EPI: 0=none, 1=+bias, 2=relu(+bias),
//      3=scores: tau=bias[z], aux=|q| row, aux2=1/|k| col, rsum += row sums
//      4=divide by max(aux,1e-9), rounded store
//      6=+bias + row sumsq, rounded; 7=row sumsq, rounded
// RND: round plain stores (EPI 0/1/2)
template <int EPI, bool TRB, bool RND>
__device__ __forceinline__ void gemm_body(
    const float* __restrict__ A, const float* __restrict__ B, float* __restrict__ C,
    int M, int N, int K, int rowBase, int colBase, int z,
    const float* __restrict__ bias, const float* __restrict__ aux,
    const float* __restrict__ aux2, float* __restrict__ rsum) {
    constexpr int BM = 128, BN = 128, BK = 32;
    constexpr int AP  = 36;
    constexpr int BPK = 136;
    constexpr int ASZ = BM * AP;
    constexpr int BSZ = TRB ? (BN * AP) : (BK * BPK);
    extern __shared__ float sm[];
    float* As = sm;
    float* Bs = sm + 2 * ASZ;

    const int tid = threadIdx.x;
    const int lane = tid & 31, warp = tid >> 5;
    const int wm = warp >> 1, wn = warp & 1;
    const int lrow = lane >> 2, lcol = lane & 3;
    const bool fullTile = (rowBase + BM <= M) && (colBase + BN <= N);

    float acc[2][8][4];
    #pragma unroll
    for (int i = 0; i < 2; i++)
        #pragma unroll
        for (int j = 0; j < 8; j++)
            #pragma unroll
            for (int e = 0; e < 4; e++) acc[i][j][e] = 0.0f;

    auto issue = [&](int ch) {
        const int kt = ch * BK;
        float* dA = As + (ch & 1) * ASZ;
        float* dB = Bs + (ch & 1) * BSZ;
        #pragma unroll
        for (int i = 0; i < 4; i++) {
            int id = i * 256 + tid;
            int row = id >> 3, c4 = (id & 7) * 4;
            int gm = rowBase + row;
            const float* src = A + (long long)(gm < M ? gm : 0) * K + kt + c4;
            cpa16(dA + row * AP + c4, src, (gm < M) ? 16 : 0);
        }
        if (!TRB) {
            #pragma unroll
            for (int i = 0; i < 4; i++) {
                int id = i * 256 + tid;
                int k = id >> 5, n4 = (id & 31) * 4;
                int gn = colBase + n4;
                const float* src = B + (long long)(kt + k) * N + (gn < N ? gn : 0);
                cpa16(dB + k * BPK + n4, src, (gn < N) ? 16 : 0);
            }
        } else {
            #pragma unroll
            for (int i = 0; i < 4; i++) {
                int id = i * 256 + tid;
                int row = id >> 3, c4 = (id & 7) * 4;
                int gn = colBase + row;
                const float* src = B + (long long)(gn < N ? gn : 0) * K + kt + c4;
                cpa16(dB + row * AP + c4, src, (gn < N) ? 16 : 0);
            }
        }
        cp_commit();
    };

    const int nch = K / BK;
    issue(0);
    for (int ch = 0; ch < nch; ch++) {
        cp_wait0();
        __syncthreads();
        if (ch + 1 < nch) issue(ch + 1);
        const float* Ab = As + (ch & 1) * ASZ;
        const float* Bb = Bs + (ch & 1) * BSZ;
        #pragma unroll
        for (int ks = 0; ks < 4; ks++) {
            const int k0 = ks * 8;
            unsigned ah[2][4];
            #pragma unroll
            for (int mt = 0; mt < 2; mt++) {
                const float* ap = Ab + (wm * 32 + mt * 16 + lrow) * AP + k0 + lcol;
                ah[mt][0] = __float_as_uint(ap[0]);
                ah[mt][1] = __float_as_uint(ap[8 * AP]);
                ah[mt][2] = __float_as_uint(ap[4]);
                ah[mt][3] = __float_as_uint(ap[8 * AP + 4]);
            }
            #pragma unroll
            for (int nt = 0; nt < 8; nt++) {
                unsigned bh0, bh1;
                if (!TRB) {
                    const float* bp = Bb + (k0 + lcol) * BPK + wn * 64 + nt * 8 + lrow;
                    bh0 = __float_as_uint(bp[0]);
                    bh1 = __float_as_uint(bp[4 * BPK]);
                } else {
                    const float* bp = Bb + (wn * 64 + nt * 8 + lrow) * AP + k0 + lcol;
                    bh0 = __float_as_uint(bp[0]);
                    bh1 = __float_as_uint(bp[4]);
                }
                #pragma unroll
                for (int mt = 0; mt < 2; mt++) mma8(acc[mt][nt], ah[mt], bh0, bh1);
            }
        }
        __syncthreads();
    }

    if (EPI == 3) {
        const float tau = bias[z];
        #pragma unroll
        for (int mt = 0; mt < 2; mt++) {
            int gm0 = rowBase + wm * 32 + mt * 16 + lrow;
            int gm1 = gm0 + 8;
            float rq0 = 1.0f / fmaxf(aux[(long long)z * M + gm0], 1e-12f);
            float rq1 = 1.0f / fmaxf(aux[(long long)z * M + gm1], 1e-12f);
            float sum0 = 0.0f, sum1 = 0.0f;
            #pragma unroll
            for (int nt = 0; nt < 8; nt++) {
                int gc = colBase + wn * 64 + nt * 8 + lcol * 2;
                float ck0 = aux2[(long long)z * N + gc];
                float ck1 = aux2[(long long)z * N + gc + 1];
                #pragma unroll
                for (int e = 0; e < 4; e++) {
                    int gm = (e < 2) ? gm0 : gm1;
                    int gn = gc + (e & 1);
                    float x = acc[mt][nt][e] * ((e < 2) ? rq0 : rq1) * ((e & 1) ? ck1 : ck0);
                    x = (x + 1.0f) * 0.5f;
                    float dd = 1.0f - x;
                    float v = rnd(fmaxf(1.0f - tau * dd * dd, 0.0f));
                    C[(long long)gm * N + gn] = v;
                    if (e < 2) sum0 += v; else sum1 += v;
                }
            }
            sum0 += __shfl_xor_sync(0xffffffffu, sum0, 1);
            sum0 += __shfl_xor_sync(0xffffffffu, sum0, 2);
            sum1 += __shfl_xor_sync(0xffffffffu, sum1, 1);
            sum1 += __shfl_xor_sync(0xffffffffu, sum1, 2);
            if (lcol == 0) {
                atomicAdd(&rsum[(long long)z * M + gm0], sum0);
                atomicAdd(&rsum[(long long)z * M + gm1], sum1);
            }
        }
        return;
    }

    if (EPI == 6 || EPI == 7) {
        #pragma unroll
        for (int mt = 0; mt < 2; mt++) {
            int gm0 = rowBase + wm * 32 + mt * 16 + lrow;
            int gm1 = gm0 + 8;
            float sum0 = 0.0f, sum1 = 0.0f;
            #pragma unroll
            for (int nt = 0; nt < 8; nt++) {
                int gc = colBase + wn * 64 + nt * 8 + lcol * 2;
                #pragma unroll
                for (int e = 0; e < 4; e++) {
                    int gm = (e < 2) ? gm0 : gm1;
                    int gn = gc + (e & 1);
                    float v = acc[mt][nt][e];
                    if (EPI == 6) v += bias[gn];
                    v = rnd(v);
                    C[(long long)gm * N + gn] = v;
                    if (e < 2) sum0 += v * v; else sum1 += v * v;
                }
            }
            sum0 += __shfl_xor_sync(0xffffffffu, sum0, 1);
            sum0 += __shfl_xor_sync(0xffffffffu, sum0, 2);
            sum1 += __shfl_xor_sync(0xffffffffu, sum1, 1);
            sum1 += __shfl_xor_sync(0xffffffffu, sum1, 2);
            if (lcol == 0) {
                atomicAdd(&rsum[gm0], sum0);
                atomicAdd(&rsum[gm1], sum1);
            }
        }
        return;
    }

    #pragma unroll
    for (int mt = 0; mt < 2; mt++) {
        int gm0 = rowBase + wm * 32 + mt * 16 + lrow;
        int gm1 = gm0 + 8;
        float rd0 = 1.0f, rd1 = 1.0f;
        if (EPI == 4) {
            if (fullTile || gm0 < M) rd0 = 1.0f / fmaxf(aux[(long long)z * M + gm0], 1e-9f);
            if (fullTile || gm1 < M) rd1 = 1.0f / fmaxf(aux[(long long)z * M + gm1], 1e-9f);
        }
        #pragma unroll
        for (int nt = 0; nt < 8; nt++) {
            int gc = colBase + wn * 64 + nt * 8 + lcol * 2;
            #pragma unroll
            for (int e = 0; e < 4; e++) {
                int gm = (e < 2) ? gm0 : gm1;
                int gn = gc + (e & 1);
                if (!fullTile && (gm >= M || gn >= N)) continue;
                float v = acc[mt][nt][e];
                if (EPI == 1) v += bias[gn];
                else if (EPI == 2) v = fmaxf(v + bias[gn], 0.0f);
                else if (EPI == 4) v *= (e < 2) ? rd0 : rd1;
                if (RND || EPI == 4) v = rnd(v);
                C[(long long)gm * N + gn] = v;
            }
        }
    }
}

// ---------------- global wrappers --------------------------------------------
template <int EPI, bool TRB, bool RND>
__global__ void __launch_bounds__(256, 2) mma_gemm(
    const float* __restrict__ Ag, const float* __restrict__ Bg, float* __restrict__ Cg,
    int M, int N, int K, long long sA, long long sB, long long sC,
    const float* __restrict__ bias, const float* __restrict__ aux,
    const float* __restrict__ aux2, float* __restrict__ rsum) {
    const int z = blockIdx.z;
    gemm_body<EPI, TRB, RND>(Ag + (long long)z * sA, Bg + (long long)z * sB,
                             Cg + (long long)z * sC, M, N, K,
                             blockIdx.y * 128, blockIdx.x * 128, z, bias, aux, aux2, rsum);
}

struct QKVArgs {
    const float* A[3];
    const float* Bm[3];
    float* C[3];
    const float* bias[3];
    float* qsq;
};
// z=0: Q projection (+bias, fused row sumsq, rounded); z=1: K, z=2: V (rounded)
__global__ void __launch_bounds__(256, 2) qkv_gemm(QKVArgs p) {
    const int z = blockIdx.z;
    const int rb = blockIdx.y * 128, cb = blockIdx.x * 128;
    if (z == 0)
        gemm_body<6, false, true>(p.A[0], p.Bm[0], p.C[0], M_, D_, D_, rb, cb, 0,
                                  p.bias[0], nullptr, nullptr, p.qsq);
    else if (z == 1)
        gemm_body<1, false, true>(p.A[1], p.Bm[1], p.C[1], M_, D_, D_, rb, cb, 0,
                                  p.bias[1], nullptr, nullptr, nullptr);
    else
        gemm_body<1, false, true>(p.A[2], p.Bm[2], p.C[2], M_, D_, D_, rb, cb, 0,
                                  p.bias[2], nullptr, nullptr, nullptr);
}

// blockIdx.x < 4: H1 = relu(K@Wr1+br1) rounded;  x >= 4: Ka = K @ CRI (raw)
__global__ void __launch_bounds__(256, 2) h1ka_gemm(
    const float* __restrict__ Kp, const float* __restrict__ Wr1,
    const float* __restrict__ br1, float* __restrict__ H1,
    const float* __restrict__ CRI, float* __restrict__ Ka) {
    const int rb = blockIdx.y * 128;
    if (blockIdx.x < 4)
        gemm_body<2, false, true>(Kp, Wr1, H1, M_, H_, D_, rb, blockIdx.x * 128, 0,
                                  br1, nullptr, nullptr, nullptr);
    else
        gemm_body<0, false, false>(Kp, CRI, Ka, M_, W2P_, D_, rb, (blockIdx.x - 4) * 128, 0,
                                   nullptr, nullptr, nullptr, nullptr);
}

constexpr int SMEM_G = (2 * 128 * 36 + 2 * 128 * 36) * 4;  // 73728 B

static float* sym(const void* s) {
    void* p = nullptr;
    cudaGetSymbolAddress(&p, s);
    return (float*)p;
}

}  // namespace

extern "C" void kernel_launch(void* const* d_in, const int* in_sizes, int n_in,
                              void* d_out, int out_size) {
    const float* q_in  = (const float*)d_in[0];
    const float* k_in  = (const float*)d_in[1];
    const float* v_in  = (const float*)d_in[2];
    const float* astro = (const float*)d_in[3];
    const float* Wq = (const float*)d_in[4];
    const float* bq = (const float*)d_in[5];
    const float* Wk = (const float*)d_in[6];
    const float* bk = (const float*)d_in[7];
    const float* Wv = (const float*)d_in[8];
    const float* bv = (const float*)d_in[9];
    const float* Wo = (const float*)d_in[10];
    const float* bo = (const float*)d_in[11];
    const float* role_matrix = (const float*)d_in[12];
    const float* Wr1 = (const float*)d_in[13];
    const float* br1 = (const float*)d_in[14];
    const float* Wr2 = (const float*)d_in[15];
    const float* astro_scale = (const float*)d_in[16];
    float* out = (float*)d_out;

    float* RoleN  = sym(g_RoleN);
    float* Q      = sym(g_Q);
    float* Kp     = sym(g_K);
    float* Vp     = sym(g_V);
    float* KB     = sym(g_KB);
    float* H1     = sym(g_H1);
    float* Wt     = sym(g_Wt);
    float* Fr     = sym(g_Fr);
    float* Ka     = sym(g_Ka);
    float* P      = sym(g_P);
    float* S      = sym(g_S);
    float* CTX    = sym(g_CTX);
    float* CRI    = sym(g_CRI);
    float* IMAT   = sym(g_IMAT);
    float* RNspec = sym(g_RNspec);
    float* QI     = sym(g_QI);
    float* KI     = sym(g_KI);
    float* VI     = sym(g_VI);
    float* Wqr    = sym(g_Wqr);
    float* Wkr    = sym(g_Wkr);
    float* Wvr    = sym(g_Wvr);
    float* Wor    = sym(g_Wor);
    float* W1r    = sym(g_W1r);
    float* W2r    = sym(g_W2r);
    float* qsq    = sym(g_qsq);
    float* qnorm  = sym(g_qnorm);
    float* ksq    = sym(g_ksq);
    float* invk   = sym(g_invk);
    float* rs     = sym(g_rs);
    float* tau    = sym(g_tau);

    cudaFuncSetAttribute(mma_gemm<0, false, false>, cudaFuncAttributeMaxDynamicSharedMemorySize, SMEM_G);
    cudaFuncSetAttribute(mma_gemm<1, false, false>, cudaFuncAttributeMaxDynamicSharedMemorySize, SMEM_G);
    cudaFuncSetAttribute(mma_gemm<3, true,  false>, cudaFuncAttributeMaxDynamicSharedMemorySize, SMEM_G);
    cudaFuncSetAttribute(mma_gemm<4, false, false>, cudaFuncAttributeMaxDynamicSharedMemorySize, SMEM_G);
    cudaFuncSetAttribute(mma_gemm<7, false, false>, cudaFuncAttributeMaxDynamicSharedMemorySize, SMEM_G);
    cudaFuncSetAttribute(qkv_gemm,  cudaFuncAttributeMaxDynamicSharedMemorySize, SMEM_G);
    cudaFuncSetAttribute(h1ka_gemm, cudaFuncAttributeMaxDynamicSharedMemorySize, SMEM_G);

    // 1. DFT matrices (rounded) + qsq zeroing
    prep_fill<<<(FN1 + FN2 + M_ + 255) / 256, 256>>>();

    // 2. pre-round external inputs -> tf32-exact copies
    RoundArgs ra;
    const float* rin[9]  = {q_in, k_in, v_in, Wq, Wk, Wv, Wo, Wr1, Wr2};
    float* rout[9]       = {QI, KI, VI, Wqr, Wkr, Wvr, Wor, W1r, W2r};
    long long rcnt[9]    = {(long long)MD, (long long)MD, (long long)MD,
                            (long long)DD, (long long)DD, (long long)DD, (long long)DD,
                            (long long)DH, (long long)HR};
    long long cum = 0;
    for (int i = 0; i < 9; i++) {
        ra.in[i]  = (const float4*)rin[i];
        ra.out[i] = (float4*)rout[i];
        cum += rcnt[i] / 4;
        ra.end4[i] = cum;
    }
    round_inputs<<<(int)((cum + 255) / 256), 256>>>(ra);

    // 3. role rows normalize + spectra (rounded)
    rownorm_kernel<<<R_, 256>>>(role_matrix, RoleN, D_);
    rnspec_kernel<<<(R_ * W2P_ + 255) / 256, 256>>>();

    // 4. Q, K, V projections in ONE launch (Q fuses row sum-of-squares)
    QKVArgs qa;
    qa.A[0] = QI; qa.A[1] = KI; qa.A[2] = VI;
    qa.Bm[0] = Wqr; qa.Bm[1] = Wkr; qa.Bm[2] = Wvr;
    qa.C[0] = Q;  qa.C[1] = Kp;  qa.C[2] = Vp;
    qa.bias[0] = bq; qa.bias[1] = bk; qa.bias[2] = bv;
    qa.qsq = qsq;
    qkv_gemm<<<dim3(8, 64, 3), 256, SMEM_G>>>(qa);

    // 5. |Q| rows; astro state + tau
    finalize_q<<<(M_ + 255) / 256, 256>>>();
    astro_kernel<<<B_, 256>>>(astro, astro_scale, out + (out_size - B_));

    // 6. H1 (role MLP layer 1) + Ka (K spectra) in ONE launch
    h1ka_gemm<<<dim3(13, 64, 1), 256, SMEM_G>>>(Kp, W1r, br1, H1, CRI, Ka);

    // 7. role logits -> softmax weights (rounded) -> Fr spectra
    mma_gemm<0, false, false><<<dim3(1, 64, 1), 256, SMEM_G>>>(
        H1, W2r, Wt, M_, R_, H_, 0, 0, 0, nullptr, nullptr, nullptr, nullptr);
    softmax64<<<M_ / 8, 256>>>(Wt);
    mma_gemm<0, false, false><<<dim3(9, 64, 1), 256, SMEM_G>>>(
        Wt, RNspec, Fr, M_, W2P_, R_, 0, 0, 0, nullptr, nullptr, nullptr, nullptr);

    // 8. binding product (rounded P; zeroes ksq), inverse DFT (rounded KB + sumsq)
    cmul_kernel<<<(int)(((long long)M_ * NF_ + 255) / 256), 256>>>();
    mma_gemm<7, false, false><<<dim3(8, 64, 1), 256, SMEM_G>>>(
        P, IMAT, KB, M_, D_, W2P_, 0, 0, 0, nullptr, nullptr, nullptr, ksq);
    finalize_k<<<(M_ + 255) / 256, 256>>>();

    // 9. scores: fused cosine normalization + Epanechnikov + rowsum (rounded S)
    mma_gemm<3, true, false><<<dim3(16, 16, B_), 256, SMEM_G>>>(
        Q, KB, S, TQ_, TK_, D_,
        (long long)TQ_ * D_, (long long)TK_ * D_, (long long)TQ_ * TK_,
        tau, qnorm, invk, rs);

    // 10. context = (S @ V) / rowsum (rounded CTX), then output projection
    mma_gemm<4, false, false><<<dim3(8, 16, B_), 256, SMEM_G>>>(
        S, Vp, CTX, TQ_, D_, TK_,
        (long long)TQ_ * TK_, (long long)TK_ * D_, (long long)TQ_ * D_,
        nullptr, rs, nullptr, nullptr);
    mma_gemm<1, false, false><<<dim3(8, 64, 1), 256, SMEM_G>>>(
        CTX, Wor, out, M_, D_, D_, 0, 0, 0, bo, nullptr, nullptr, nullptr);
}

// round 16
// speedup vs baseline: 3.2387x; 1.0551x over previous
#include <cuda_runtime.h>
#include <math.h>

namespace {

constexpr int B_   = 4;
constexpr int TQ_  = 2048;
constexpr int TK_  = 2048;
constexpr int D_   = 1024;
constexpr int R_   = 64;
constexpr int H_   = 512;
constexpr int NF_  = D_ / 2 + 1;   // 513 rfft bins
constexpr int W2_  = 2 * NF_;      // 1026 (re | im)
constexpr int W2P_ = 1056;         // padded to multiple of BK=32
constexpr int M_   = B_ * TQ_;     // 8192 rows
constexpr size_t MD = (size_t)M_ * D_;
constexpr size_t DD = (size_t)D_ * D_;
constexpr size_t DH = (size_t)D_ * H_;
constexpr size_t HR = (size_t)H_ * R_;

// ---------------- scratch ----------------------------------------------------
__device__ __align__(128) float g_CRI[D_ * W2P_];
__device__ __align__(128) float g_IMAT[W2P_ * D_];
__device__ __align__(128) float g_RoleN[R_ * D_];
__device__ __align__(128) float g_RNspec[R_ * W2P_];
__device__ __align__(128) float g_Q[MD];
__device__ __align__(128) float g_K[MD];
__device__ __align__(128) float g_V[MD];
__device__ __align__(128) float g_KB[MD];
__device__ __align__(128) float g_H1[M_ * H_];
__device__ __align__(128) float g_Wt[M_ * R_];
__device__ __align__(128) float g_Fr[(size_t)M_ * W2P_];
__device__ __align__(128) float g_Ka[(size_t)M_ * W2P_];
__device__ __align__(128) float g_P[(size_t)M_ * W2P_];   // pad cols never written -> stay 0
__device__ __align__(128) float g_S[(size_t)B_ * TQ_ * TK_];
__device__ __align__(128) float g_CTX[MD];
// tf32-pre-rounded copies of external inputs
__device__ __align__(128) float g_QI[MD];
__device__ __align__(128) float g_KI[MD];
__device__ __align__(128) float g_VI[MD];
__device__ __align__(128) float g_Wqr[DD];
__device__ __align__(128) float g_Wkr[DD];
__device__ __align__(128) float g_Wvr[DD];
__device__ __align__(128) float g_Wor[DD];
__device__ __align__(128) float g_W1r[DH];
__device__ __align__(128) float g_W2r[HR];
__device__ __align__(128) float g_qsq[M_];
__device__ __align__(128) float g_qnorm[M_];
__device__ __align__(128) float g_ksq[M_];
__device__ __align__(128) float g_invk[M_];
__device__ __align__(128) float g_rs[M_];
__device__ __align__(128) float g_tau[B_];

// ---------------- tf32 rounding helpers ---------------------------------------
__device__ __forceinline__ unsigned tf32u(float x) {
    unsigned u;
    asm("cvt.rna.tf32.f32 %0, %1;" : "=r"(u) : "f"(x));
    return u;
}
__device__ __forceinline__ float rnd(float v) { return __uint_as_float(tf32u(v)); }

// ---------------- merged prep: fills + input rounding + role rownorm ---------
constexpr int FN1 = D_ * W2P_;
constexpr int FN2 = W2P_ * D_;
constexpr int NBF = (FN1 + FN2 + M_ + 255) / 256;

struct RoundArgs {
    const float4* in[9];
    float4* out[9];
    long long end4[9];   // cumulative end (in float4 units)
    int nbr;             // blocks for rounding section
    const float* role_matrix;
};

__global__ void prep_all(RoundArgs ra) {
    int blk = blockIdx.x;
    if (blk < NBF) {                       // --- fills + qsq zero ---
        int idx = blk * 256 + threadIdx.x;
        if (idx < FN1) {                   // CRI[d][f]
            int d = idx / W2P_, f = idx % W2P_;
            float v = 0.0f;
            if (f < W2_) {
                int fr = (f < NF_) ? f : (f - NF_);
                int m  = (int)(((long long)fr * d) % D_);
                float a = (float)m * (6.283185307179586f / (float)D_);
                v = (f < NF_) ? cosf(a) : -sinf(a);
            }
            g_CRI[idx] = rnd(v);
        } else if (idx < FN1 + FN2) {      // IMAT[f][d]
            int j = idx - FN1;
            int f = j / D_, d = j % D_;
            float v = 0.0f;
            if (f < W2_) {
                int fr = (f < NF_) ? f : (f - NF_);
                int m  = (int)(((long long)fr * d) % D_);
                float a = (float)m * (6.283185307179586f / (float)D_);
                if (f < NF_) {
                    float c = (fr == 0 || fr == D_ / 2) ? 1.0f : 2.0f;
                    v = c * cosf(a) * (1.0f / (float)D_);
                } else {
                    v = (fr == 0 || fr == D_ / 2) ? 0.0f : (-2.0f / (float)D_) * sinf(a);
                }
            }
            g_IMAT[j] = rnd(v);
        } else if (idx < FN1 + FN2 + M_) {
            g_qsq[idx - FN1 - FN2] = 0.0f;
        }
        return;
    }
    if (blk < NBF + ra.nbr) {              // --- vectorized input rounding ---
        long long i = (long long)(blk - NBF) * 256 + threadIdx.x;
        if (i >= ra.end4[8]) return;
        int s = 0;
        while (i >= ra.end4[s]) s++;
        long long base = (s == 0) ? 0 : ra.end4[s - 1];
        long long j = i - base;
        float4 v = ra.in[s][j];
        v.x = rnd(v.x); v.y = rnd(v.y); v.z = rnd(v.z); v.w = rnd(v.w);
        ra.out[s][j] = v;
        return;
    }
    {                                      // --- role row l2-normalize ---
        int row = blk - NBF - ra.nbr;      // 0..R_-1
        const float* p = ra.role_matrix + (size_t)row * D_;
        float s = 0.0f;
        for (int c = threadIdx.x; c < D_; c += 256) { float v = p[c]; s += v * v; }
        __shared__ float red[256];
        red[threadIdx.x] = s;
        __syncthreads();
        for (int o = 128; o > 0; o >>= 1) {
            if (threadIdx.x < o) red[threadIdx.x] += red[threadIdx.x + o];
            __syncthreads();
        }
        float inv = 1.0f / fmaxf(sqrtf(red[0]), 1e-12f);
        float* q = g_RoleN + (size_t)row * D_;
        for (int c = threadIdx.x; c < D_; c += 256) q[c] = p[c] * inv;
    }
}

// ---------------- RNspec = RoleN @ CRI  (tiled SIMT mini-GEMM) ---------------
// grid = W2P_/16 = 66 blocks; block computes all 64 r x 16 w outputs.
// Accumulation over d is sequential (same order as before -> bitwise identical).
constexpr int RW = 16;    // w per block
constexpr int RDC = 128;  // d chunk
__global__ void __launch_bounds__(256) rnspec_kernel() {
    __shared__ float RoleNT[RDC][66];   // [d][r], stride 66 (even -> float2 ok)
    __shared__ float CRIs[RDC][RW];     // [d][w]
    const int w0 = blockIdx.x * RW;
    const int tid = threadIdx.x;
    const int w2 = (tid & 7) * 2;       // 2 w per thread
    const int r2 = (tid >> 3) * 2;      // 2 r per thread
    float a00 = 0.f, a01 = 0.f, a10 = 0.f, a11 = 0.f;
    for (int dc = 0; dc < D_; dc += RDC) {
        __syncthreads();
        for (int i = tid; i < R_ * RDC; i += 256) {
            int r = i >> 7, dd = i & (RDC - 1);
            RoleNT[dd][r] = g_RoleN[(size_t)r * D_ + dc + dd];
        }
        for (int i = tid; i < RDC * RW; i += 256) {
            int dd = i >> 4, w = i & (RW - 1);
            CRIs[dd][w] = g_CRI[(size_t)(dc + dd) * W2P_ + w0 + w];
        }
        __syncthreads();
        #pragma unroll 4
        for (int dd = 0; dd < RDC; dd++) {
            float2 rn = *reinterpret_cast<const float2*>(&RoleNT[dd][r2]);
            float2 cw = *reinterpret_cast<const float2*>(&CRIs[dd][w2]);
            a00 = fmaf(rn.x, cw.x, a00);
            a01 = fmaf(rn.x, cw.y, a01);
            a10 = fmaf(rn.y, cw.x, a10);
            a11 = fmaf(rn.y, cw.y, a11);
        }
    }
    g_RNspec[(size_t)r2 * W2P_ + w0 + w2]           = rnd(a00);
    g_RNspec[(size_t)r2 * W2P_ + w0 + w2 + 1]       = rnd(a01);
    g_RNspec[(size_t)(r2 + 1) * W2P_ + w0 + w2]     = rnd(a10);
    g_RNspec[(size_t)(r2 + 1) * W2P_ + w0 + w2 + 1] = rnd(a11);
}

// ---------------- finalize_k --------------------------------------------------
__global__ void finalize_k() {
    int i = blockIdx.x * blockDim.x + threadIdx.x;
    if (i < M_) {
        g_invk[i] = 1.0f / fmaxf(sqrtf(g_ksq[i]), 1e-12f);
        g_rs[i] = 0.0f;
    }
}

// ---------------- astro: qnorm = sqrt(qsq) + state/tau (merged) --------------
__global__ void astro_kernel(const float* __restrict__ astro_in,
                             const float* __restrict__ astro_scale,
                             float* __restrict__ out_state) {
    int b = blockIdx.x;
    float s = 0.0f;
    for (int t = threadIdx.x; t < TQ_; t += blockDim.x) {
        float qn = sqrtf(g_qsq[b * TQ_ + t]);
        g_qnorm[b * TQ_ + t] = qn;
        s += qn;
    }
    __shared__ float red[256];
    red[threadIdx.x] = s;
    __syncthreads();
    for (int o = 128; o > 0; o >>= 1) {
        if (threadIdx.x < o) red[threadIdx.x] += red[threadIdx.x + o];
        __syncthreads();
    }
    if (threadIdx.x == 0) {
        float mean_surprise = red[0] / (32.0f * (float)TQ_);
        float ns = 0.95f * astro_in[b] + 0.05f * mean_surprise;
        g_tau[b] = fmaxf(1.0f + astro_scale[0] * ns, 0.001f);
        out_state[b] = ns;
    }
}

// ---------------- softmax over R=64 (rounded stores) -------------------------
__global__ void softmax64(float* __restrict__ x) {
    int warp = (blockIdx.x * blockDim.x + threadIdx.x) >> 5;
    int lane = threadIdx.x & 31;
    if (warp >= M_) return;
    float* p = x + (size_t)warp * R_;
    float v0 = p[lane], v1 = p[lane + 32];
    float m = fmaxf(v0, v1);
    #pragma unroll
    for (int o = 16; o > 0; o >>= 1) m = fmaxf(m, __shfl_xor_sync(0xffffffffu, m, o));
    float e0 = expf(v0 - m), e1 = expf(v1 - m);
    float sum = e0 + e1;
    #pragma unroll
    for (int o = 16; o > 0; o >>= 1) sum += __shfl_xor_sync(0xffffffffu, sum, o);
    float inv = 1.0f / sum;
    p[lane] = rnd(e0 * inv);
    p[lane + 32] = rnd(e1 * inv);
}

// ---------------- complex product (rounded stores; + ksq zero) ---------------
__global__ void cmul_kernel() {
    long long i = (long long)blockIdx.x * blockDim.x + threadIdx.x;
    if (i >= (long long)M_ * NF_) return;
    if (i < M_) g_ksq[i] = 0.0f;
    long long row = i / NF_;
    int f = (int)(i % NF_);
    const float* a = g_Ka + row * W2P_;
    const float* b = g_Fr + row * W2P_;
    float ar = a[f], ai = a[NF_ + f];
    float br = b[f], bi = b[NF_ + f];
    g_P[row * W2P_ + f]       = rnd(ar * br - ai * bi);
    g_P[row * W2P_ + NF_ + f] = rnd(ar * bi + ai * br);
}

// ---------------- cp.async helpers -------------------------------------------
__device__ __forceinline__ void cpa16(float* dst, const float* src, int sz) {
    unsigned d = (unsigned)__cvta_generic_to_shared(dst);
    asm volatile("cp.async.cg.shared.global [%0], [%1], 16, %2;" :: "r"(d), "l"(src), "r"(sz));
}
__device__ __forceinline__ void cp_commit() { asm volatile("cp.async.commit_group;"); }
__device__ __forceinline__ void cp_wait0()  { asm volatile("cp.async.wait_group 0;"); }

__device__ __forceinline__ void mma8(float* c, const unsigned* a, unsigned b0, unsigned b1) {
    asm volatile(
        "mma.sync.aligned.m16n8k8.row.col.f32.tf32.tf32.f32 "
        "{%0,%1,%2,%3},{%4,%5,%6,%7},{%8,%9},{%0,%1,%2,%3};"
        : "+f"(c[0]), "+f"(c[1]), "+f"(c[2]), "+f"(c[3])
        : "r"(a[0]), "r"(a[1]), "r"(a[2]), "r"(a[3]), "r"(b0), "r"(b1));
}

// ---------------- tf32 GEMM body (operands pre-rounded; no inner cvt) --------
// C[M,N] = A[M,K] row-major times B (B[K][N] if !TRB, B[N][K] if TRB)
// EPI: 0=none, 1=+bias, 2=relu(+bias),
//      3=scores: tau=bias[z], aux=|q| row, aux2=1/|k| col, rsum += row sums
//      4=divide by max(aux,1e-9), rounded store
//      6=+bias + row sumsq, rounded; 7=row sumsq, rounded
// RND: round plain stores (EPI 0/1/2)
template <int EPI, bool TRB, bool RND>
__device__ __forceinline__ void gemm_body(
    const float* __restrict__ A, const float* __restrict__ B, float* __restrict__ C,
    int M, int N, int K, int rowBase, int colBase, int z,
    const float* __restrict__ bias, const float* __restrict__ aux,
    const float* __restrict__ aux2, float* __restrict__ rsum) {
    constexpr int BM = 128, BN = 128, BK = 32;
    constexpr int AP  = 36;
    constexpr int BPK = 136;
    constexpr int ASZ = BM * AP;
    constexpr int BSZ = TRB ? (BN * AP) : (BK * BPK);
    extern __shared__ float sm[];
    float* As = sm;
    float* Bs = sm + 2 * ASZ;

    const int tid = threadIdx.x;
    const int lane = tid & 31, warp = tid >> 5;
    const int wm = warp >> 1, wn = warp & 1;
    const int lrow = lane >> 2, lcol = lane & 3;
    const bool fullTile = (rowBase + BM <= M) && (colBase + BN <= N);

    float acc[2][8][4];
    #pragma unroll
    for (int i = 0; i < 2; i++)
        #pragma unroll
        for (int j = 0; j < 8; j++)
            #pragma unroll
            for (int e = 0; e < 4; e++) acc[i][j][e] = 0.0f;

    auto issue = [&](int ch) {
        const int kt = ch * BK;
        float* dA = As + (ch & 1) * ASZ;
        float* dB = Bs + (ch & 1) * BSZ;
        #pragma unroll
        for (int i = 0; i < 4; i++) {
            int id = i * 256 + tid;
            int row = id >> 3, c4 = (id & 7) * 4;
            int gm = rowBase + row;
            const float* src = A + (long long)(gm < M ? gm : 0) * K + kt + c4;
            cpa16(dA + row * AP + c4, src, (gm < M) ? 16 : 0);
        }
        if (!TRB) {
            #pragma unroll
            for (int i = 0; i < 4; i++) {
                int id = i * 256 + tid;
                int k = id >> 5, n4 = (id & 31) * 4;
                int gn = colBase + n4;
                const float* src = B + (long long)(kt + k) * N + (gn < N ? gn : 0);
                cpa16(dB + k * BPK + n4, src, (gn < N) ? 16 : 0);
            }
        } else {
            #pragma unroll
            for (int i = 0; i < 4; i++) {
                int id = i * 256 + tid;
                int row = id >> 3, c4 = (id & 7) * 4;
                int gn = colBase + row;
                const float* src = B + (long long)(gn < N ? gn : 0) * K + kt + c4;
                cpa16(dB + row * AP + c4, src, (gn < N) ? 16 : 0);
            }
        }
        cp_commit();
    };

    const int nch = K / BK;
    issue(0);
    for (int ch = 0; ch < nch; ch++) {
        cp_wait0();
        __syncthreads();
        if (ch + 1 < nch) issue(ch + 1);
        const float* Ab = As + (ch & 1) * ASZ;
        const float* Bb = Bs + (ch & 1) * BSZ;
        #pragma unroll
        for (int ks = 0; ks < 4; ks++) {
            const int k0 = ks * 8;
            unsigned ah[2][4];
            #pragma unroll
            for (int mt = 0; mt < 2; mt++) {
                const float* ap = Ab + (wm * 32 + mt * 16 + lrow) * AP + k0 + lcol;
                ah[mt][0] = __float_as_uint(ap[0]);
                ah[mt][1] = __float_as_uint(ap[8 * AP]);
                ah[mt][2] = __float_as_uint(ap[4]);
                ah[mt][3] = __float_as_uint(ap[8 * AP + 4]);
            }
            #pragma unroll
            for (int nt = 0; nt < 8; nt++) {
                unsigned bh0, bh1;
                if (!TRB) {
                    const float* bp = Bb + (k0 + lcol) * BPK + wn * 64 + nt * 8 + lrow;
                    bh0 = __float_as_uint(bp[0]);
                    bh1 = __float_as_uint(bp[4 * BPK]);
                } else {
                    const float* bp = Bb + (wn * 64 + nt * 8 + lrow) * AP + k0 + lcol;
                    bh0 = __float_as_uint(bp[0]);
                    bh1 = __float_as_uint(bp[4]);
                }
                #pragma unroll
                for (int mt = 0; mt < 2; mt++) mma8(acc[mt][nt], ah[mt], bh0, bh1);
            }
        }
        __syncthreads();
    }

    if (EPI == 3) {
        const float tau = bias[z];
        #pragma unroll
        for (int mt = 0; mt < 2; mt++) {
            int gm0 = rowBase + wm * 32 + mt * 16 + lrow;
            int gm1 = gm0 + 8;
            float rq0 = 1.0f / fmaxf(aux[(long long)z * M + gm0], 1e-12f);
            float rq1 = 1.0f / fmaxf(aux[(long long)z * M + gm1], 1e-12f);
            float sum0 = 0.0f, sum1 = 0.0f;
            #pragma unroll
            for (int nt = 0; nt < 8; nt++) {
                int gc = colBase + wn * 64 + nt * 8 + lcol * 2;
                float ck0 = aux2[(long long)z * N + gc];
                float ck1 = aux2[(long long)z * N + gc + 1];
                #pragma unroll
                for (int e = 0; e < 4; e++) {
                    int gm = (e < 2) ? gm0 : gm1;
                    int gn = gc + (e & 1);
                    float x = acc[mt][nt][e] * ((e < 2) ? rq0 : rq1) * ((e & 1) ? ck1 : ck0);
                    x = (x + 1.0f) * 0.5f;
                    float dd = 1.0f - x;
                    float v = rnd(fmaxf(1.0f - tau * dd * dd, 0.0f));
                    C[(long long)gm * N + gn] = v;
                    if (e < 2) sum0 += v; else sum1 += v;
                }
            }
            sum0 += __shfl_xor_sync(0xffffffffu, sum0, 1);
            sum0 += __shfl_xor_sync(0xffffffffu, sum0, 2);
            sum1 += __shfl_xor_sync(0xffffffffu, sum1, 1);
            sum1 += __shfl_xor_sync(0xffffffffu, sum1, 2);
            if (lcol == 0) {
                atomicAdd(&rsum[(long long)z * M + gm0], sum0);
                atomicAdd(&rsum[(long long)z * M + gm1], sum1);
            }
        }
        return;
    }

    if (EPI == 6 || EPI == 7) {
        #pragma unroll
        for (int mt = 0; mt < 2; mt++) {
            int gm0 = rowBase + wm * 32 + mt * 16 + lrow;
            int gm1 = gm0 + 8;
            float sum0 = 0.0f, sum1 = 0.0f;
            #pragma unroll
            for (int nt = 0; nt < 8; nt++) {
                int gc = colBase + wn * 64 + nt * 8 + lcol * 2;
                #pragma unroll
                for (int e = 0; e < 4; e++) {
                    int gm = (e < 2) ? gm0 : gm1;
                    int gn = gc + (e & 1);
                    float v = acc[mt][nt][e];
                    if (EPI == 6) v += bias[gn];
                    v = rnd(v);
                    C[(long long)gm * N + gn] = v;
                    if (e < 2) sum0 += v * v; else sum1 += v * v;
                }
            }
            sum0 += __shfl_xor_sync(0xffffffffu, sum0, 1);
            sum0 += __shfl_xor_sync(0xffffffffu, sum0, 2);
            sum1 += __shfl_xor_sync(0xffffffffu, sum1, 1);
            sum1 += __shfl_xor_sync(0xffffffffu, sum1, 2);
            if (lcol == 0) {
                atomicAdd(&rsum[gm0], sum0);
                atomicAdd(&rsum[gm1], sum1);
            }
        }
        return;
    }

    #pragma unroll
    for (int mt = 0; mt < 2; mt++) {
        int gm0 = rowBase + wm * 32 + mt * 16 + lrow;
        int gm1 = gm0 + 8;
        float rd0 = 1.0f, rd1 = 1.0f;
        if (EPI == 4) {
            if (fullTile || gm0 < M) rd0 = 1.0f / fmaxf(aux[(long long)z * M + gm0], 1e-9f);
            if (fullTile || gm1 < M) rd1 = 1.0f / fmaxf(aux[(long long)z * M + gm1], 1e-9f);
        }
        #pragma unroll
        for (int nt = 0; nt < 8; nt++) {
            int gc = colBase + wn * 64 + nt * 8 + lcol * 2;
            #pragma unroll
            for (int e = 0; e < 4; e++) {
                int gm = (e < 2) ? gm0 : gm1;
                int gn = gc + (e & 1);
                if (!fullTile && (gm >= M || gn >= N)) continue;
                float v = acc[mt][nt][e];
                if (EPI == 1) v += bias[gn];
                else if (EPI == 2) v = fmaxf(v + bias[gn], 0.0f);
                else if (EPI == 4) v *= (e < 2) ? rd0 : rd1;
                if (RND || EPI == 4) v = rnd(v);
                C[(long long)gm * N + gn] = v;
            }
        }
    }
}

// ---------------- global wrappers --------------------------------------------
template <int EPI, bool TRB, bool RND>
__global__ void __launch_bounds__(256, 2) mma_gemm(
    const float* __restrict__ Ag, const float* __restrict__ Bg, float* __restrict__ Cg,
    int M, int N, int K, long long sA, long long sB, long long sC,
    const float* __restrict__ bias, const float* __restrict__ aux,
    const float* __restrict__ aux2, float* __restrict__ rsum) {
    const int z = blockIdx.z;
    gemm_body<EPI, TRB, RND>(Ag + (long long)z * sA, Bg + (long long)z * sB,
                             Cg + (long long)z * sC, M, N, K,
                             blockIdx.y * 128, blockIdx.x * 128, z, bias, aux, aux2, rsum);
}

struct QKVArgs {
    const float* A[3];
    const float* Bm[3];
    float* C[3];
    const float* bias[3];
    float* qsq;
};
// z=0: Q projection (+bias, fused row sumsq, rounded); z=1: K, z=2: V (rounded)
__global__ void __launch_bounds__(256, 2) qkv_gemm(QKVArgs p) {
    const int z = blockIdx.z;
    const int rb = blockIdx.y * 128, cb = blockIdx.x * 128;
    if (z == 0)
        gemm_body<6, false, true>(p.A[0], p.Bm[0], p.C[0], M_, D_, D_, rb, cb, 0,
                                  p.bias[0], nullptr, nullptr, p.qsq);
    else if (z == 1)
        gemm_body<1, false, true>(p.A[1], p.Bm[1], p.C[1], M_, D_, D_, rb, cb, 0,
                                  p.bias[1], nullptr, nullptr, nullptr);
    else
        gemm_body<1, false, true>(p.A[2], p.Bm[2], p.C[2], M_, D_, D_, rb, cb, 0,
                                  p.bias[2], nullptr, nullptr, nullptr);
}

// blockIdx.x < 4: H1 = relu(K@Wr1+br1) rounded;  x >= 4: Ka = K @ CRI (raw)
__global__ void __launch_bounds__(256, 2) h1ka_gemm(
    const float* __restrict__ Kp, const float* __restrict__ Wr1,
    const float* __restrict__ br1, float* __restrict__ H1,
    const float* __restrict__ CRI, float* __restrict__ Ka) {
    const int rb = blockIdx.y * 128;
    if (blockIdx.x < 4)
        gemm_body<2, false, true>(Kp, Wr1, H1, M_, H_, D_, rb, blockIdx.x * 128, 0,
                                  br1, nullptr, nullptr, nullptr);
    else
        gemm_body<0, false, false>(Kp, CRI, Ka, M_, W2P_, D_, rb, (blockIdx.x - 4) * 128, 0,
                                   nullptr, nullptr, nullptr, nullptr);
}

constexpr int SMEM_G = (2 * 128 * 36 + 2 * 128 * 36) * 4;  // 73728 B

static float* sym(const void* s) {
    void* p = nullptr;
    cudaGetSymbolAddress(&p, s);
    return (float*)p;
}

}  // namespace

extern "C" void kernel_launch(void* const* d_in, const int* in_sizes, int n_in,
                              void* d_out, int out_size) {
    const float* q_in  = (const float*)d_in[0];
    const float* k_in  = (const float*)d_in[1];
    const float* v_in  = (const float*)d_in[2];
    const float* astro = (const float*)d_in[3];
    const float* Wq = (const float*)d_in[4];
    const float* bq = (const float*)d_in[5];
    const float* Wk = (const float*)d_in[6];
    const float* bk = (const float*)d_in[7];
    const float* Wv = (const float*)d_in[8];
    const float* bv = (const float*)d_in[9];
    const float* Wo = (const float*)d_in[10];
    const float* bo = (const float*)d_in[11];
    const float* role_matrix = (const float*)d_in[12];
    const float* Wr1 = (const float*)d_in[13];
    const float* br1 = (const float*)d_in[14];
    const float* Wr2 = (const float*)d_in[15];
    const float* astro_scale = (const float*)d_in[16];
    float* out = (float*)d_out;

    float* Q      = sym(g_Q);
    float* Kp     = sym(g_K);
    float* Vp     = sym(g_V);
    float* KB     = sym(g_KB);
    float* H1     = sym(g_H1);
    float* Wt     = sym(g_Wt);
    float* Fr     = sym(g_Fr);
    float* Ka     = sym(g_Ka);
    float* P      = sym(g_P);
    float* S      = sym(g_S);
    float* CTX    = sym(g_CTX);
    float* CRI    = sym(g_CRI);
    float* IMAT   = sym(g_IMAT);
    float* RNspec = sym(g_RNspec);
    float* QI     = sym(g_QI);
    float* KI     = sym(g_KI);
    float* VI     = sym(g_VI);
    float* Wqr    = sym(g_Wqr);
    float* Wkr    = sym(g_Wkr);
    float* Wvr    = sym(g_Wvr);
    float* Wor    = sym(g_Wor);
    float* W1r    = sym(g_W1r);
    float* W2r    = sym(g_W2r);
    float* qsq    = sym(g_qsq);
    float* qnorm  = sym(g_qnorm);
    float* ksq    = sym(g_ksq);
    float* invk   = sym(g_invk);
    float* rs     = sym(g_rs);
    float* tau    = sym(g_tau);

    cudaFuncSetAttribute(mma_gemm<0, false, false>, cudaFuncAttributeMaxDynamicSharedMemorySize, SMEM_G);
    cudaFuncSetAttribute(mma_gemm<1, false, false>, cudaFuncAttributeMaxDynamicSharedMemorySize, SMEM_G);
    cudaFuncSetAttribute(mma_gemm<3, true,  false>, cudaFuncAttributeMaxDynamicSharedMemorySize, SMEM_G);
    cudaFuncSetAttribute(mma_gemm<4, false, false>, cudaFuncAttributeMaxDynamicSharedMemorySize, SMEM_G);
    cudaFuncSetAttribute(mma_gemm<7, false, false>, cudaFuncAttributeMaxDynamicSharedMemorySize, SMEM_G);
    cudaFuncSetAttribute(qkv_gemm,  cudaFuncAttributeMaxDynamicSharedMemorySize, SMEM_G);
    cudaFuncSetAttribute(h1ka_gemm, cudaFuncAttributeMaxDynamicSharedMemorySize, SMEM_G);

    // 1. merged prep: DFT fills + qsq zero + input rounding + role rownorm
    RoundArgs ra;
    const float* rin[9]  = {q_in, k_in, v_in, Wq, Wk, Wv, Wo, Wr1, Wr2};
    float* rout[9]       = {QI, KI, VI, Wqr, Wkr, Wvr, Wor, W1r, W2r};
    long long rcnt[9]    = {(long long)MD, (long long)MD, (long long)MD,
                            (long long)DD, (long long)DD, (long long)DD, (long long)DD,
                            (long long)DH, (long long)HR};
    long long cum = 0;
    for (int i = 0; i < 9; i++) {
        ra.in[i]  = (const float4*)rin[i];
        ra.out[i] = (float4*)rout[i];
        cum += rcnt[i] / 4;
        ra.end4[i] = cum;
    }
    ra.nbr = (int)((cum + 255) / 256);
    ra.role_matrix = role_matrix;
    prep_all<<<NBF + ra.nbr + R_, 256>>>(ra);

    // 2. role spectra (tiled mini-GEMM, 66 blocks)
    rnspec_kernel<<<W2P_ / 16, 256>>>();

    // 3. Q, K, V projections in ONE launch (Q fuses row sum-of-squares)
    QKVArgs qa;
    qa.A[0] = QI; qa.A[1] = KI; qa.A[2] = VI;
    qa.Bm[0] = Wqr; qa.Bm[1] = Wkr; qa.Bm[2] = Wvr;
    qa.C[0] = Q;  qa.C[1] = Kp;  qa.C[2] = Vp;
    qa.bias[0] = bq; qa.bias[1] = bk; qa.bias[2] = bv;
    qa.qsq = qsq;
    qkv_gemm<<<dim3(8, 64, 3), 256, SMEM_G>>>(qa);

    // 4. |Q| rows + astro state + tau (merged)
    astro_kernel<<<B_, 256>>>(astro, astro_scale, out + (out_size - B_));

    // 5. H1 (role MLP layer 1) + Ka (K spectra) in ONE launch
    h1ka_gemm<<<dim3(13, 64, 1), 256, SMEM_G>>>(Kp, W1r, br1, H1, CRI, Ka);

    // 6. role logits -> softmax weights (rounded) -> Fr spectra
    mma_gemm<0, false, false><<<dim3(1, 64, 1), 256, SMEM_G>>>(
        H1, W2r, Wt, M_, R_, H_, 0, 0, 0, nullptr, nullptr, nullptr, nullptr);
    softmax64<<<M_ / 8, 256>>>(Wt);
    mma_gemm<0, false, false><<<dim3(9, 64, 1), 256, SMEM_G>>>(
        Wt, RNspec, Fr, M_, W2P_, R_, 0, 0, 0, nullptr, nullptr, nullptr, nullptr);

    // 7. binding product (rounded P; zeroes ksq), inverse DFT (rounded KB + sumsq)
    cmul_kernel<<<(int)(((long long)M_ * NF_ + 255) / 256), 256>>>();
    mma_gemm<7, false, false><<<dim3(8, 64, 1), 256, SMEM_G>>>(
        P, IMAT, KB, M_, D_, W2P_, 0, 0, 0, nullptr, nullptr, nullptr, ksq);
    finalize_k<<<(M_ + 255) / 256, 256>>>();

    // 8. scores: fused cosine normalization + Epanechnikov + rowsum (rounded S)
    mma_gemm<3, true, false><<<dim3(16, 16, B_), 256, SMEM_G>>>(
        Q, KB, S, TQ_, TK_, D_,
        (long long)TQ_ * D_, (long long)TK_ * D_, (long long)TQ_ * TK_,
        tau, qnorm, invk, rs);

    // 9. context = (S @ V) / rowsum (rounded CTX), then output projection
    mma_gemm<4, false, false><<<dim3(8, 16, B_), 256, SMEM_G>>>(
        S, Vp, CTX, TQ_, D_, TK_,
        (long long)TQ_ * TK_, (long long)TK_ * D_, (long long)TQ_ * D_,
        nullptr, rs, nullptr, nullptr);
    mma_gemm<1, false, false><<<dim3(8, 64, 1), 256, SMEM_G>>>(
        CTX, Wor, out, M_, D_, D_, 0, 0, 0, bo, nullptr, nullptr, nullptr);
}